// round 2
// baseline (speedup 1.0000x reference)
#include <cuda_runtime.h>
#include <math.h>

// ---------------- scratch (static __device__, allocation-free) ----------------
__device__ float g_sg [256 * 10000];        // savgol output
__device__ float g_y0 [256 * 64 * 624];     // conv block 0 out (b,c,p); reused as layer1 hs
__device__ float g_seq[77 * 256 * 128];     // conv block 1 out, (t,b,c)
__device__ float g_xp [77 * 256 * 1024];    // lstm input projection (t,b,4H), reused per layer
__device__ float g_hs0[77 * 256 * 256];     // layer0 hidden sequence (t,b,H)
__device__ float g_h0 [256 * 256];          // zero initial hidden
__device__ float g_cc [256 * 256];          // cell state (in-place per step)
__device__ float g_f1 [256 * 512];
__device__ float g_f2 [256 * 512];

// SG(11,3) interior smoothing taps (symmetric): [-36,9,44,69,84,89,84,69,44,9,-36]/429
__constant__ float c_sg[11] = {
    -36.f/429.f, 9.f/429.f, 44.f/429.f, 69.f/429.f, 84.f/429.f, 89.f/429.f,
    84.f/429.f, 69.f/429.f, 44.f/429.f, 9.f/429.f, -36.f/429.f };

// ---------------- savgol ----------------
// mode='interp' edges: LS cubic fit over the 11 edge samples at t=0..10,
// evaluated at edge positions. Normal equations G a = m, power sums hardcoded.
__device__ __forceinline__ void sg_fit(const float* __restrict__ xw, double a[4]) {
    double m0 = 0, m1 = 0, m2 = 0, m3 = 0;
    #pragma unroll
    for (int w = 0; w < 11; w++) {
        double y = (double)xw[w]; double t = (double)w;
        m0 += y; m1 += y * t; m2 += y * t * t; m3 += y * t * t * t;
    }
    double M[4][5] = {
        {11.0,    55.0,     385.0,     3025.0,    m0},
        {55.0,    385.0,    3025.0,    25333.0,   m1},
        {385.0,   3025.0,   25333.0,   220825.0,  m2},
        {3025.0,  25333.0,  220825.0,  1978405.0, m3}};
    #pragma unroll
    for (int i = 0; i < 4; i++) {
        double p = M[i][i];
        #pragma unroll
        for (int j = i; j < 5; j++) M[i][j] /= p;
        #pragma unroll
        for (int r = 0; r < 4; r++) {
            if (r != i) {
                double f = M[r][i];
                #pragma unroll
                for (int j = i; j < 5; j++) M[r][j] -= f * M[i][j];
            }
        }
    }
    a[0] = M[0][4]; a[1] = M[1][4]; a[2] = M[2][4]; a[3] = M[3][4];
}

__global__ __launch_bounds__(256) void savgol_kernel(const float* __restrict__ x) {
    int b = blockIdx.y;
    int i = blockIdx.x * 256 + threadIdx.x;
    if (i >= 10000) return;
    const float* xr = x + (size_t)b * 10000;
    float* o = g_sg + (size_t)b * 10000;
    if (i >= 5 && i < 9995) {
        float acc = 0.f;
        #pragma unroll
        for (int j = 0; j < 11; j++) acc = fmaf(xr[i - 5 + j], c_sg[j], acc);
        o[i] = acc;
    } else if (i < 5) {
        double a[4]; sg_fit(xr, a);
        double t = (double)i;
        o[i] = (float)(a[0] + t * (a[1] + t * (a[2] + t * a[3])));
    } else {
        double a[4]; sg_fit(xr + 9989, a);
        double t = (double)(i - 9989);   // 9995..9999 -> 6..10
        o[i] = (float)(a[0] + t * (a[1] + t * (a[2] + t * a[3])));
    }
}

// ---------------- conv block 0: conv(1->64,k16,s8)+bias -> relu -> pool2 -> BN ----------------
// pooled p uses conv positions 2p, 2p+1 -> input cols [16p, 16p+23]. 624 pooled pos.
__global__ __launch_bounds__(256) void conv0_kernel(
    const float* __restrict__ w, const float* __restrict__ bias,
    const float* __restrict__ bg, const float* __restrict__ bb,
    const float* __restrict__ bm, const float* __restrict__ bv) {
    __shared__ float in_s[2064];
    __shared__ float ws[64][17];
    __shared__ float scs[64], shs[64], bss[64];
    int b = blockIdx.y;
    int p0 = blockIdx.x * 128;
    int tid = threadIdx.x;
    int base = 16 * p0;
    for (int i = tid; i < 2064; i += 256) {
        int col = base + i;
        in_s[i] = (col < 10000) ? g_sg[(size_t)b * 10000 + col] : 0.f;
    }
    for (int i = tid; i < 1024; i += 256) ws[i >> 4][i & 15] = w[i];
    if (tid < 64) {
        float sc = bg[tid] * rsqrtf(bv[tid] + 1e-5f);
        scs[tid] = sc;
        shs[tid] = bb[tid] - bm[tid] * sc;
        bss[tid] = bias[tid];
    }
    __syncthreads();
    int p = p0 + (tid & 127);
    int cb = (tid >> 7) * 32;
    if (p >= 624) return;
    float xr[24];
    int lb = 16 * (tid & 127);
    #pragma unroll
    for (int k = 0; k < 24; k++) xr[k] = in_s[lb + k];
    #pragma unroll 4
    for (int c = cb; c < cb + 32; c++) {
        float s1 = 0.f, s2 = 0.f;
        #pragma unroll
        for (int k = 0; k < 16; k++) {
            float wv = ws[c][k];
            s1 = fmaf(wv, xr[k], s1);
            s2 = fmaf(wv, xr[k + 8], s2);
        }
        float m = fmaxf(fmaxf(s1, s2) + bss[c], 0.f);
        g_y0[((size_t)b * 64 + c) * 624 + p] = scs[c] * m + shs[c];
    }
}

// ---------------- conv block 1: conv(64->128,k8,s4)+bias -> relu -> pool2 -> BN ----------------
// 77 pooled positions; pooled p uses conv pos 2p,2p+1 -> cols [8p, 8p+11].
// Block: 8 pooled p, 128 threads (32 oc-groups x 4 pos-groups), 4oc x 4pos microtile.
// Writes (t,b,c) layout for the xproj GEMM.
__global__ __launch_bounds__(128) void conv1_kernel(
    const float* __restrict__ w, const float* __restrict__ bias,
    const float* __restrict__ bg, const float* __restrict__ bb,
    const float* __restrict__ bm, const float* __restrict__ bv) {
    __shared__ float in_s[64][68];
    __shared__ float ws[4][8][128];
    __shared__ float scs[128], shs[128], bss[128];
    int b = blockIdx.y;
    int p0 = blockIdx.x * 8;
    int tid = threadIdx.x;
    int cg = tid & 31, pg = tid >> 5;

    for (int i = tid; i < 64 * 68; i += 128) {
        int ic = i / 68, cc = i % 68;
        int col = 8 * p0 + cc;
        in_s[ic][cc] = (col < 624) ? g_y0[((size_t)b * 64 + ic) * 624 + col] : 0.f;
    }
    {
        float sc = bg[tid] * rsqrtf(bv[tid] + 1e-5f);
        scs[tid] = sc;
        shs[tid] = bb[tid] - bm[tid] * sc;
        bss[tid] = bias[tid];
    }
    float acc[4][4];
    #pragma unroll
    for (int i = 0; i < 4; i++)
        #pragma unroll
        for (int j = 0; j < 4; j++) acc[i][j] = 0.f;

    for (int ic0 = 0; ic0 < 64; ic0 += 4) {
        __syncthreads();
        #pragma unroll
        for (int icl = 0; icl < 4; icl++) {
            const float4* src = (const float4*)(w + ((size_t)tid * 64 + ic0 + icl) * 8);
            float4 v0 = src[0], v1 = src[1];
            ws[icl][0][tid] = v0.x; ws[icl][1][tid] = v0.y;
            ws[icl][2][tid] = v0.z; ws[icl][3][tid] = v0.w;
            ws[icl][4][tid] = v1.x; ws[icl][5][tid] = v1.y;
            ws[icl][6][tid] = v1.z; ws[icl][7][tid] = v1.w;
        }
        __syncthreads();
        #pragma unroll
        for (int icl = 0; icl < 4; icl++) {
            #pragma unroll
            for (int t = 0; t < 8; t++) {
                float4 w4 = *(const float4*)&ws[icl][t][cg * 4];
                #pragma unroll
                for (int qc = 0; qc < 4; qc++) {
                    float iv = in_s[ic0 + icl][16 * pg + 4 * qc + t];
                    acc[0][qc] = fmaf(w4.x, iv, acc[0][qc]);
                    acc[1][qc] = fmaf(w4.y, iv, acc[1][qc]);
                    acc[2][qc] = fmaf(w4.z, iv, acc[2][qc]);
                    acc[3][qc] = fmaf(w4.w, iv, acc[3][qc]);
                }
            }
        }
    }
    #pragma unroll
    for (int pp = 0; pp < 2; pp++) {
        int p = p0 + 2 * pg + pp;
        if (p >= 77) continue;
        float ov[4];
        #pragma unroll
        for (int i = 0; i < 4; i++) {
            int oc = 4 * cg + i;
            float m = fmaxf(acc[i][2 * pp], acc[i][2 * pp + 1]);
            float v = fmaxf(m + bss[oc], 0.f);
            ov[i] = scs[oc] * v + shs[oc];
        }
        *(float4*)&g_seq[((size_t)p * 256 + b) * 128 + 4 * cg] =
            make_float4(ov[0], ov[1], ov[2], ov[3]);
    }
}

// ---------------- input-projection GEMM: g_xp = A @ Wih^T + (bih + bhh) ----------------
// src=0: A=g_seq (K=128); src=1: A=g_hs0 (K=256). M=19712, N=1024.
// 128x128 tile, 256 threads, 8x8 microtile, K-chunk 16.
__global__ __launch_bounds__(256) void gemm_xproj_kernel(
    int src, const float* __restrict__ Wih,
    const float* __restrict__ b1, const float* __restrict__ b2) {
    __shared__ float As[16][132];
    __shared__ float Ws[16][132];
    const int K = src ? 256 : 128;
    const float* A = src ? g_hs0 : g_seq;
    int n0 = blockIdx.x * 128, m0 = blockIdx.y * 128;
    int tid = threadIdx.x;
    int lr = tid >> 2, lq = tid & 3;       // loader: row (0..63, +64), k-quad
    int tx = tid & 15, ty = tid >> 4;      // compute: n-tile, m-tile
    float acc[8][8];
    #pragma unroll
    for (int i = 0; i < 8; i++)
        #pragma unroll
        for (int j = 0; j < 8; j++) acc[i][j] = 0.f;

    for (int k0 = 0; k0 < K; k0 += 16) {
        __syncthreads();
        {
            float4 v;
            v = *(const float4*)&A[(size_t)(m0 + lr) * K + k0 + 4 * lq];
            As[4*lq+0][lr] = v.x; As[4*lq+1][lr] = v.y; As[4*lq+2][lr] = v.z; As[4*lq+3][lr] = v.w;
            v = *(const float4*)&A[(size_t)(m0 + lr + 64) * K + k0 + 4 * lq];
            As[4*lq+0][lr+64] = v.x; As[4*lq+1][lr+64] = v.y; As[4*lq+2][lr+64] = v.z; As[4*lq+3][lr+64] = v.w;
            v = *(const float4*)&Wih[(size_t)(n0 + lr) * K + k0 + 4 * lq];
            Ws[4*lq+0][lr] = v.x; Ws[4*lq+1][lr] = v.y; Ws[4*lq+2][lr] = v.z; Ws[4*lq+3][lr] = v.w;
            v = *(const float4*)&Wih[(size_t)(n0 + lr + 64) * K + k0 + 4 * lq];
            Ws[4*lq+0][lr+64] = v.x; Ws[4*lq+1][lr+64] = v.y; Ws[4*lq+2][lr+64] = v.z; Ws[4*lq+3][lr+64] = v.w;
        }
        __syncthreads();
        #pragma unroll
        for (int kk = 0; kk < 16; kk++) {
            float a[8], bb[8];
            *(float4*)&a[0]  = *(const float4*)&As[kk][8 * ty];
            *(float4*)&a[4]  = *(const float4*)&As[kk][8 * ty + 4];
            *(float4*)&bb[0] = *(const float4*)&Ws[kk][8 * tx];
            *(float4*)&bb[4] = *(const float4*)&Ws[kk][8 * tx + 4];
            #pragma unroll
            for (int i = 0; i < 8; i++)
                #pragma unroll
                for (int j = 0; j < 8; j++)
                    acc[i][j] = fmaf(a[i], bb[j], acc[i][j]);
        }
    }
    float bv[8];
    #pragma unroll
    for (int j = 0; j < 8; j++) {
        int n = n0 + 8 * tx + j;
        bv[j] = b1[n] + b2[n];
    }
    #pragma unroll
    for (int i = 0; i < 8; i++) {
        size_t row = (size_t)(m0 + 8 * ty + i) * 1024 + n0 + 8 * tx;
        float4 o0 = make_float4(acc[i][0]+bv[0], acc[i][1]+bv[1], acc[i][2]+bv[2], acc[i][3]+bv[3]);
        float4 o1 = make_float4(acc[i][4]+bv[4], acc[i][5]+bv[5], acc[i][6]+bv[6], acc[i][7]+bv[7]);
        *(float4*)&g_xp[row]     = o0;
        *(float4*)&g_xp[row + 4] = o1;
    }
}

// ---------------- zero init for h0 / c ----------------
__global__ __launch_bounds__(256) void zero_kernel() {
    int i = blockIdx.x * 256 + threadIdx.x;
    if (i < 256 * 256) { g_h0[i] = 0.f; g_cc[i] = 0.f; }
}

__device__ __forceinline__ float sigf(float x) { return 1.f / (1.f + expf(-x)); }

// ---------------- fused LSTM step: gates = xp[t] + h_prev @ Whh^T; update c,h ----------------
// grid (8 hidden-tiles of 32, 8 batch-tiles of 32), 256 threads.
// Each thread: 2 batch x 2 hidden x 4 gates.
__global__ __launch_bounds__(256) void lstm_step_kernel(
    int t, int layer, const float* __restrict__ Whh) {
    __shared__ float hs_[32][33];
    __shared__ float ws_[128][33];
    const float* xp_t = g_xp + (size_t)t * 256 * 1024;
    float* hs = layer ? g_y0 : g_hs0;
    const float* h_prev = (t == 0) ? g_h0 : hs + (size_t)(t - 1) * 65536;
    float* h_out = hs + (size_t)t * 65536;
    int n0 = blockIdx.x * 32;   // hidden tile
    int b0 = blockIdx.y * 32;   // batch tile
    int tid = threadIdx.x;
    int tb = tid & 15, th = tid >> 4;
    int lrow = tid >> 3, lkq = tid & 7;
    float acc[4][2][2];
    #pragma unroll
    for (int g = 0; g < 4; g++)
        #pragma unroll
        for (int i = 0; i < 2; i++)
            #pragma unroll
            for (int j = 0; j < 2; j++) acc[g][i][j] = 0.f;

    for (int k0 = 0; k0 < 256; k0 += 32) {
        __syncthreads();
        {
            float4 v = *(const float4*)&h_prev[(size_t)(b0 + lrow) * 256 + k0 + 4 * lkq];
            hs_[lrow][4*lkq+0] = v.x; hs_[lrow][4*lkq+1] = v.y;
            hs_[lrow][4*lkq+2] = v.z; hs_[lrow][4*lkq+3] = v.w;
            #pragma unroll
            for (int j = 0; j < 4; j++) {
                int lr = lrow + 32 * j;                 // 0..127
                int grow = (lr >> 5) * 256 + n0 + (lr & 31);
                float4 wv = *(const float4*)&Whh[(size_t)grow * 256 + k0 + 4 * lkq];
                ws_[lr][4*lkq+0] = wv.x; ws_[lr][4*lkq+1] = wv.y;
                ws_[lr][4*lkq+2] = wv.z; ws_[lr][4*lkq+3] = wv.w;
            }
        }
        __syncthreads();
        #pragma unroll
        for (int kk = 0; kk < 32; kk++) {
            float h0v = hs_[2*tb][kk], h1v = hs_[2*tb+1][kk];
            #pragma unroll
            for (int g = 0; g < 4; g++) {
                float w0 = ws_[g*32 + 2*th][kk], w1 = ws_[g*32 + 2*th + 1][kk];
                acc[g][0][0] = fmaf(h0v, w0, acc[g][0][0]);
                acc[g][0][1] = fmaf(h0v, w1, acc[g][0][1]);
                acc[g][1][0] = fmaf(h1v, w0, acc[g][1][0]);
                acc[g][1][1] = fmaf(h1v, w1, acc[g][1][1]);
            }
        }
    }
    #pragma unroll
    for (int bi = 0; bi < 2; bi++) {
        #pragma unroll
        for (int hi = 0; hi < 2; hi++) {
            int b = b0 + 2 * tb + bi;
            int h = n0 + 2 * th + hi;
            const float* xr = xp_t + (size_t)b * 1024;
            float gi = acc[0][bi][hi] + xr[h];
            float gf = acc[1][bi][hi] + xr[256 + h];
            float gg = acc[2][bi][hi] + xr[512 + h];
            float go = acc[3][bi][hi] + xr[768 + h];
            int ci = b * 256 + h;
            float c = sigf(gf) * g_cc[ci] + sigf(gi) * tanhf(gg);
            g_cc[ci] = c;
            h_out[ci] = sigf(go) * tanhf(c);
        }
    }
}

// ---------------- FC head: out = [relu](A @ W^T + b) ----------------
// stage 0: A=layer1 h_last (K=256) -> g_f1 (N=512), relu
// stage 1: A=g_f1 (K=512)          -> g_f2 (N=512), relu
// stage 2: A=g_f2 (K=512)          -> dout (N=256)
__global__ __launch_bounds__(256) void fc_kernel(
    int stage, const float* __restrict__ W, const float* __restrict__ bias,
    float* __restrict__ dout) {
    __shared__ float As[32][33];
    __shared__ float Ws[32][33];
    const float* A; float* out; int K, N; int relu;
    if (stage == 0) { A = g_y0 + (size_t)76 * 65536; out = g_f1; K = 256; N = 512; relu = 1; }
    else if (stage == 1) { A = g_f1; out = g_f2; K = 512; N = 512; relu = 1; }
    else { A = g_f2; out = dout; K = 512; N = 256; relu = 0; }
    int n0 = blockIdx.x * 32, m0 = blockIdx.y * 32;
    int tid = threadIdx.x;
    int lrow = tid >> 3, lkq = tid & 7;
    int ty = tid >> 4, tx = tid & 15;
    float acc[2][2] = {{0.f, 0.f}, {0.f, 0.f}};
    for (int k0 = 0; k0 < K; k0 += 32) {
        __syncthreads();
        {
            float4 va = *(const float4*)&A[(size_t)(m0 + lrow) * K + k0 + 4 * lkq];
            As[lrow][4*lkq+0] = va.x; As[lrow][4*lkq+1] = va.y;
            As[lrow][4*lkq+2] = va.z; As[lrow][4*lkq+3] = va.w;
            float4 vw = *(const float4*)&W[(size_t)(n0 + lrow) * K + k0 + 4 * lkq];
            Ws[lrow][4*lkq+0] = vw.x; Ws[lrow][4*lkq+1] = vw.y;
            Ws[lrow][4*lkq+2] = vw.z; Ws[lrow][4*lkq+3] = vw.w;
        }
        __syncthreads();
        #pragma unroll
        for (int kk = 0; kk < 32; kk++) {
            float a0 = As[2*ty][kk], a1 = As[2*ty+1][kk];
            float w0 = Ws[2*tx][kk], w1 = Ws[2*tx+1][kk];
            acc[0][0] = fmaf(a0, w0, acc[0][0]);
            acc[0][1] = fmaf(a0, w1, acc[0][1]);
            acc[1][0] = fmaf(a1, w0, acc[1][0]);
            acc[1][1] = fmaf(a1, w1, acc[1][1]);
        }
    }
    #pragma unroll
    for (int i = 0; i < 2; i++) {
        #pragma unroll
        for (int j = 0; j < 2; j++) {
            int m = m0 + 2 * ty + i, n = n0 + 2 * tx + j;
            float v = acc[i][j] + bias[n];
            if (relu) v = fmaxf(v, 0.f);
            out[(size_t)m * N + n] = v;
        }
    }
}

// ---------------- launch ----------------
extern "C" void kernel_launch(void* const* d_in, const int* in_sizes, int n_in,
                              void* d_out, int out_size) {
    const float* x       = (const float*)d_in[0];
    const float* conv_w0 = (const float*)d_in[1];
    const float* conv_b0 = (const float*)d_in[2];
    const float* bn_g0   = (const float*)d_in[3];
    const float* bn_b0   = (const float*)d_in[4];
    const float* bn_m0   = (const float*)d_in[5];
    const float* bn_v0   = (const float*)d_in[6];
    const float* conv_w1 = (const float*)d_in[7];
    const float* conv_b1 = (const float*)d_in[8];
    const float* bn_g1   = (const float*)d_in[9];
    const float* bn_b1   = (const float*)d_in[10];
    const float* bn_m1   = (const float*)d_in[11];
    const float* bn_v1   = (const float*)d_in[12];
    const float* Wih0    = (const float*)d_in[13];
    const float* Whh0    = (const float*)d_in[14];
    const float* bih0    = (const float*)d_in[15];
    const float* bhh0    = (const float*)d_in[16];
    const float* Wih1    = (const float*)d_in[17];
    const float* Whh1    = (const float*)d_in[18];
    const float* bih1    = (const float*)d_in[19];
    const float* bhh1    = (const float*)d_in[20];
    const float* fc0_w   = (const float*)d_in[21];
    const float* fc0_b   = (const float*)d_in[22];
    const float* fc1_w   = (const float*)d_in[23];
    const float* fc1_b   = (const float*)d_in[24];
    const float* out_w   = (const float*)d_in[25];
    const float* out_b   = (const float*)d_in[26];
    float* out = (float*)d_out;

    savgol_kernel<<<dim3(40, 256), 256>>>(x);
    conv0_kernel<<<dim3(5, 256), 256>>>(conv_w0, conv_b0, bn_g0, bn_b0, bn_m0, bn_v0);
    conv1_kernel<<<dim3(10, 256), 128>>>(conv_w1, conv_b1, bn_g1, bn_b1, bn_m1, bn_v1);

    // Layer 0
    gemm_xproj_kernel<<<dim3(8, 154), 256>>>(0, Wih0, bih0, bhh0);
    zero_kernel<<<256, 256>>>();
    for (int t = 0; t < 77; t++)
        lstm_step_kernel<<<dim3(8, 8), 256>>>(t, 0, Whh0);

    // Layer 1
    gemm_xproj_kernel<<<dim3(8, 154), 256>>>(1, Wih1, bih1, bhh1);
    zero_kernel<<<256, 256>>>();
    for (int t = 0; t < 77; t++)
        lstm_step_kernel<<<dim3(8, 8), 256>>>(t, 1, Whh1);

    // Head
    fc_kernel<<<dim3(16, 8), 256>>>(0, fc0_w, fc0_b, out);
    fc_kernel<<<dim3(16, 8), 256>>>(1, fc1_w, fc1_b, out);
    fc_kernel<<<dim3(8, 8), 256>>>(2, out_w, out_b, out);
}

// round 3
// speedup vs baseline: 1.0089x; 1.0089x over previous
#include <cuda_runtime.h>
#include <math.h>

// ---------------- scratch (static __device__, allocation-free) ----------------
__device__ float g_sg [256 * 10000];        // savgol output
__device__ float g_y0 [256 * 64 * 624];     // conv block 0 out (b,c,p); reused as layer1 hs
__device__ float g_seq[77 * 256 * 128];     // conv block 1 out, (t,b,c)
__device__ float g_xp [77 * 256 * 1024];    // lstm input projection (t,b,4H), reused per layer
__device__ float g_hs0[77 * 256 * 256];     // layer0 hidden sequence (t,b,H)
__device__ float g_cc [256 * 256];          // cell state (in-place per step)
__device__ float g_gates[256 * 1024];       // per-step gate pre-activations
__device__ float g_f1 [256 * 512];
__device__ float g_f2 [256 * 512];

__device__ unsigned g_bcnt = 0;             // grid barrier arrive counter
__device__ unsigned g_bgen = 0;             // grid barrier generation (monotonic)

// SG(11,3) interior smoothing taps (symmetric): [-36,9,44,69,84,89,84,69,44,9,-36]/429
__constant__ float c_sg[11] = {
    -36.f/429.f, 9.f/429.f, 44.f/429.f, 69.f/429.f, 84.f/429.f, 89.f/429.f,
    84.f/429.f, 69.f/429.f, 44.f/429.f, 9.f/429.f, -36.f/429.f };

// ---------------- savgol ----------------
__device__ __forceinline__ void sg_fit(const float* __restrict__ xw, double a[4]) {
    double m0 = 0, m1 = 0, m2 = 0, m3 = 0;
    #pragma unroll
    for (int w = 0; w < 11; w++) {
        double y = (double)xw[w]; double t = (double)w;
        m0 += y; m1 += y * t; m2 += y * t * t; m3 += y * t * t * t;
    }
    double M[4][5] = {
        {11.0,    55.0,     385.0,     3025.0,    m0},
        {55.0,    385.0,    3025.0,    25333.0,   m1},
        {385.0,   3025.0,   25333.0,   220825.0,  m2},
        {3025.0,  25333.0,  220825.0,  1978405.0, m3}};
    #pragma unroll
    for (int i = 0; i < 4; i++) {
        double p = M[i][i];
        #pragma unroll
        for (int j = i; j < 5; j++) M[i][j] /= p;
        #pragma unroll
        for (int r = 0; r < 4; r++) {
            if (r != i) {
                double f = M[r][i];
                #pragma unroll
                for (int j = i; j < 5; j++) M[r][j] -= f * M[i][j];
            }
        }
    }
    a[0] = M[0][4]; a[1] = M[1][4]; a[2] = M[2][4]; a[3] = M[3][4];
}

__global__ __launch_bounds__(256) void savgol_kernel(const float* __restrict__ x) {
    int b = blockIdx.y;
    int i = blockIdx.x * 256 + threadIdx.x;
    if (i >= 10000) return;
    const float* xr = x + (size_t)b * 10000;
    float* o = g_sg + (size_t)b * 10000;
    if (i >= 5 && i < 9995) {
        float acc = 0.f;
        #pragma unroll
        for (int j = 0; j < 11; j++) acc = fmaf(xr[i - 5 + j], c_sg[j], acc);
        o[i] = acc;
    } else if (i < 5) {
        double a[4]; sg_fit(xr, a);
        double t = (double)i;
        o[i] = (float)(a[0] + t * (a[1] + t * (a[2] + t * a[3])));
    } else {
        double a[4]; sg_fit(xr + 9989, a);
        double t = (double)(i - 9989);
        o[i] = (float)(a[0] + t * (a[1] + t * (a[2] + t * a[3])));
    }
}

// ---------------- conv block 0 ----------------
__global__ __launch_bounds__(256) void conv0_kernel(
    const float* __restrict__ w, const float* __restrict__ bias,
    const float* __restrict__ bg, const float* __restrict__ bb,
    const float* __restrict__ bm, const float* __restrict__ bv) {
    __shared__ float in_s[2064];
    __shared__ float ws[64][17];
    __shared__ float scs[64], shs[64], bss[64];
    int b = blockIdx.y;
    int p0 = blockIdx.x * 128;
    int tid = threadIdx.x;
    int base = 16 * p0;
    for (int i = tid; i < 2064; i += 256) {
        int col = base + i;
        in_s[i] = (col < 10000) ? g_sg[(size_t)b * 10000 + col] : 0.f;
    }
    for (int i = tid; i < 1024; i += 256) ws[i >> 4][i & 15] = w[i];
    if (tid < 64) {
        float sc = bg[tid] * rsqrtf(bv[tid] + 1e-5f);
        scs[tid] = sc;
        shs[tid] = bb[tid] - bm[tid] * sc;
        bss[tid] = bias[tid];
    }
    __syncthreads();
    int p = p0 + (tid & 127);
    int cb = (tid >> 7) * 32;
    if (p >= 624) return;
    float xr[24];
    int lb = 16 * (tid & 127);
    #pragma unroll
    for (int k = 0; k < 24; k++) xr[k] = in_s[lb + k];
    #pragma unroll 4
    for (int c = cb; c < cb + 32; c++) {
        float s1 = 0.f, s2 = 0.f;
        #pragma unroll
        for (int k = 0; k < 16; k++) {
            float wv = ws[c][k];
            s1 = fmaf(wv, xr[k], s1);
            s2 = fmaf(wv, xr[k + 8], s2);
        }
        float m = fmaxf(fmaxf(s1, s2) + bss[c], 0.f);
        g_y0[((size_t)b * 64 + c) * 624 + p] = scs[c] * m + shs[c];
    }
}

// ---------------- conv block 1 ----------------
__global__ __launch_bounds__(128) void conv1_kernel(
    const float* __restrict__ w, const float* __restrict__ bias,
    const float* __restrict__ bg, const float* __restrict__ bb,
    const float* __restrict__ bm, const float* __restrict__ bv) {
    __shared__ float in_s[64][68];
    __shared__ float ws[4][8][128];
    __shared__ float scs[128], shs[128], bss[128];
    int b = blockIdx.y;
    int p0 = blockIdx.x * 8;
    int tid = threadIdx.x;
    int cg = tid & 31, pg = tid >> 5;

    for (int i = tid; i < 64 * 68; i += 128) {
        int ic = i / 68, cc = i % 68;
        int col = 8 * p0 + cc;
        in_s[ic][cc] = (col < 624) ? g_y0[((size_t)b * 64 + ic) * 624 + col] : 0.f;
    }
    {
        float sc = bg[tid] * rsqrtf(bv[tid] + 1e-5f);
        scs[tid] = sc;
        shs[tid] = bb[tid] - bm[tid] * sc;
        bss[tid] = bias[tid];
    }
    float acc[4][4];
    #pragma unroll
    for (int i = 0; i < 4; i++)
        #pragma unroll
        for (int j = 0; j < 4; j++) acc[i][j] = 0.f;

    for (int ic0 = 0; ic0 < 64; ic0 += 4) {
        __syncthreads();
        #pragma unroll
        for (int icl = 0; icl < 4; icl++) {
            const float4* src = (const float4*)(w + ((size_t)tid * 64 + ic0 + icl) * 8);
            float4 v0 = src[0], v1 = src[1];
            ws[icl][0][tid] = v0.x; ws[icl][1][tid] = v0.y;
            ws[icl][2][tid] = v0.z; ws[icl][3][tid] = v0.w;
            ws[icl][4][tid] = v1.x; ws[icl][5][tid] = v1.y;
            ws[icl][6][tid] = v1.z; ws[icl][7][tid] = v1.w;
        }
        __syncthreads();
        #pragma unroll
        for (int icl = 0; icl < 4; icl++) {
            #pragma unroll
            for (int t = 0; t < 8; t++) {
                float4 w4 = *(const float4*)&ws[icl][t][cg * 4];
                #pragma unroll
                for (int qc = 0; qc < 4; qc++) {
                    float iv = in_s[ic0 + icl][16 * pg + 4 * qc + t];
                    acc[0][qc] = fmaf(w4.x, iv, acc[0][qc]);
                    acc[1][qc] = fmaf(w4.y, iv, acc[1][qc]);
                    acc[2][qc] = fmaf(w4.z, iv, acc[2][qc]);
                    acc[3][qc] = fmaf(w4.w, iv, acc[3][qc]);
                }
            }
        }
    }
    #pragma unroll
    for (int pp = 0; pp < 2; pp++) {
        int p = p0 + 2 * pg + pp;
        if (p >= 77) continue;
        float ov[4];
        #pragma unroll
        for (int i = 0; i < 4; i++) {
            int oc = 4 * cg + i;
            float m = fmaxf(acc[i][2 * pp], acc[i][2 * pp + 1]);
            float v = fmaxf(m + bss[oc], 0.f);
            ov[i] = scs[oc] * v + shs[oc];
        }
        *(float4*)&g_seq[((size_t)p * 256 + b) * 128 + 4 * cg] =
            make_float4(ov[0], ov[1], ov[2], ov[3]);
    }
}

// ---------------- input-projection GEMM: g_xp = A @ Wih^T + (bih + bhh) ----------------
__global__ __launch_bounds__(256) void gemm_xproj_kernel(
    int src, const float* __restrict__ Wih,
    const float* __restrict__ b1, const float* __restrict__ b2) {
    __shared__ float As[16][132];
    __shared__ float Ws[16][132];
    const int K = src ? 256 : 128;
    const float* A = src ? g_hs0 : g_seq;
    int n0 = blockIdx.x * 128, m0 = blockIdx.y * 128;
    int tid = threadIdx.x;
    int lr = tid >> 2, lq = tid & 3;
    int tx = tid & 15, ty = tid >> 4;
    float acc[8][8];
    #pragma unroll
    for (int i = 0; i < 8; i++)
        #pragma unroll
        for (int j = 0; j < 8; j++) acc[i][j] = 0.f;

    for (int k0 = 0; k0 < K; k0 += 16) {
        __syncthreads();
        {
            float4 v;
            v = *(const float4*)&A[(size_t)(m0 + lr) * K + k0 + 4 * lq];
            As[4*lq+0][lr] = v.x; As[4*lq+1][lr] = v.y; As[4*lq+2][lr] = v.z; As[4*lq+3][lr] = v.w;
            v = *(const float4*)&A[(size_t)(m0 + lr + 64) * K + k0 + 4 * lq];
            As[4*lq+0][lr+64] = v.x; As[4*lq+1][lr+64] = v.y; As[4*lq+2][lr+64] = v.z; As[4*lq+3][lr+64] = v.w;
            v = *(const float4*)&Wih[(size_t)(n0 + lr) * K + k0 + 4 * lq];
            Ws[4*lq+0][lr] = v.x; Ws[4*lq+1][lr] = v.y; Ws[4*lq+2][lr] = v.z; Ws[4*lq+3][lr] = v.w;
            v = *(const float4*)&Wih[(size_t)(n0 + lr + 64) * K + k0 + 4 * lq];
            Ws[4*lq+0][lr+64] = v.x; Ws[4*lq+1][lr+64] = v.y; Ws[4*lq+2][lr+64] = v.z; Ws[4*lq+3][lr+64] = v.w;
        }
        __syncthreads();
        #pragma unroll
        for (int kk = 0; kk < 16; kk++) {
            float a[8], bb[8];
            *(float4*)&a[0]  = *(const float4*)&As[kk][8 * ty];
            *(float4*)&a[4]  = *(const float4*)&As[kk][8 * ty + 4];
            *(float4*)&bb[0] = *(const float4*)&Ws[kk][8 * tx];
            *(float4*)&bb[4] = *(const float4*)&Ws[kk][8 * tx + 4];
            #pragma unroll
            for (int i = 0; i < 8; i++)
                #pragma unroll
                for (int j = 0; j < 8; j++)
                    acc[i][j] = fmaf(a[i], bb[j], acc[i][j]);
        }
    }
    float bv[8];
    #pragma unroll
    for (int j = 0; j < 8; j++) {
        int n = n0 + 8 * tx + j;
        bv[j] = b1[n] + b2[n];
    }
    #pragma unroll
    for (int i = 0; i < 8; i++) {
        size_t row = (size_t)(m0 + 8 * ty + i) * 1024 + n0 + 8 * tx;
        float4 o0 = make_float4(acc[i][0]+bv[0], acc[i][1]+bv[1], acc[i][2]+bv[2], acc[i][3]+bv[3]);
        float4 o1 = make_float4(acc[i][4]+bv[4], acc[i][5]+bv[5], acc[i][6]+bv[6], acc[i][7]+bv[7]);
        *(float4*)&g_xp[row]     = o0;
        *(float4*)&g_xp[row + 4] = o1;
    }
}

// ---------------- persistent LSTM layer ----------------
// 128 CTAs x 128 threads, all co-resident. CTA = (batch-tile bt of 64) x (gate-col tile ct of 32).
// Whh tile (32 cols x 256 k) cached in smem for all 77 steps (k-major, padded).
// Per step: stage h_prev tile -> GEMM (4x4 microtile) + xp add -> gates | barrier |
// pointwise gate update | barrier.
#define NCTA 128
#define WS_STRIDE 36
#define HS_STRIDE 68
#define LSTM_SMEM ((256 * WS_STRIDE + 256 * HS_STRIDE) * 4)

__device__ __forceinline__ void gridbar(int tid) {
    __syncthreads();
    __threadfence();
    if (tid == 0) {
        unsigned gen = *(volatile unsigned*)&g_bgen;
        unsigned my = atomicAdd(&g_bcnt, 1);
        if (my == NCTA - 1) {
            g_bcnt = 0;
            __threadfence();
            atomicAdd(&g_bgen, 1);
        } else {
            while (*(volatile unsigned*)&g_bgen == gen) { }
        }
        __threadfence();
    }
    __syncthreads();
}

__device__ __forceinline__ float sigf(float x) { return 1.f / (1.f + expf(-x)); }

__global__ __launch_bounds__(128) void lstm_persist_kernel(
    int layer, const float* __restrict__ Whh) {
    extern __shared__ float sm[];
    float* ws_s = sm;                         // [256][WS_STRIDE] k-major Whh tile
    float* hs_s = sm + 256 * WS_STRIDE;       // [256][HS_STRIDE] k-major h tile

    int tid = threadIdx.x;
    int blk = blockIdx.x;
    int bt = blk >> 5;                        // 0..3  (batch tile of 64)
    int ct = blk & 31;                        // 0..31 (gate-col tile of 32)
    int b0 = bt * 64;
    int colbase = ct * 32;
    float* hs = layer ? g_y0 : g_hs0;

    // cache Whh tile (transposed to k-major)
    {
        int j = tid & 31;                     // col within tile
        int q = tid >> 5;                     // k quarter
        const float* wr = Whh + (size_t)(colbase + j) * 256;
        for (int k = q * 64; k < q * 64 + 64; k += 4) {
            float4 wv = *(const float4*)&wr[k];
            ws_s[(k + 0) * WS_STRIDE + j] = wv.x;
            ws_s[(k + 1) * WS_STRIDE + j] = wv.y;
            ws_s[(k + 2) * WS_STRIDE + j] = wv.z;
            ws_s[(k + 3) * WS_STRIDE + j] = wv.w;
        }
    }

    int tx = tid & 7;                         // 8 col-groups of 4
    int ty = tid >> 3;                        // 16 batch-groups of 4
    int gtid = blk * 128 + tid;               // pointwise id
    int pidx = gtid * 4;                      // 4 consecutive (b,h) units
    int pb = pidx >> 8;
    int ph = pidx & 255;

    for (int t = 0; t < 77; t++) {
        // ---- stage h_prev tile (k-major) ----
        __syncthreads();
        {
            int bb = tid & 63;
            int half = tid >> 6;
            if (t == 0) {
                for (int k = half * 128; k < half * 128 + 128; k += 4) {
                    hs_s[(k + 0) * HS_STRIDE + bb] = 0.f;
                    hs_s[(k + 1) * HS_STRIDE + bb] = 0.f;
                    hs_s[(k + 2) * HS_STRIDE + bb] = 0.f;
                    hs_s[(k + 3) * HS_STRIDE + bb] = 0.f;
                }
            } else {
                const float* hp = hs + (size_t)(t - 1) * 65536 + (size_t)(b0 + bb) * 256;
                for (int k = half * 128; k < half * 128 + 128; k += 4) {
                    float4 hv = *(const float4*)&hp[k];
                    hs_s[(k + 0) * HS_STRIDE + bb] = hv.x;
                    hs_s[(k + 1) * HS_STRIDE + bb] = hv.y;
                    hs_s[(k + 2) * HS_STRIDE + bb] = hv.z;
                    hs_s[(k + 3) * HS_STRIDE + bb] = hv.w;
                }
            }
        }
        __syncthreads();

        // ---- recurrent GEMM: 4 batch x 4 cols per thread ----
        float acc[4][4];
        #pragma unroll
        for (int i = 0; i < 4; i++)
            #pragma unroll
            for (int j = 0; j < 4; j++) acc[i][j] = 0.f;

        #pragma unroll 4
        for (int k = 0; k < 256; k++) {
            float4 av = *(const float4*)&hs_s[k * HS_STRIDE + 4 * ty];
            float4 bv = *(const float4*)&ws_s[k * WS_STRIDE + 4 * tx];
            acc[0][0] = fmaf(av.x, bv.x, acc[0][0]);
            acc[0][1] = fmaf(av.x, bv.y, acc[0][1]);
            acc[0][2] = fmaf(av.x, bv.z, acc[0][2]);
            acc[0][3] = fmaf(av.x, bv.w, acc[0][3]);
            acc[1][0] = fmaf(av.y, bv.x, acc[1][0]);
            acc[1][1] = fmaf(av.y, bv.y, acc[1][1]);
            acc[1][2] = fmaf(av.y, bv.z, acc[1][2]);
            acc[1][3] = fmaf(av.y, bv.w, acc[1][3]);
            acc[2][0] = fmaf(av.z, bv.x, acc[2][0]);
            acc[2][1] = fmaf(av.z, bv.y, acc[2][1]);
            acc[2][2] = fmaf(av.z, bv.z, acc[2][2]);
            acc[2][3] = fmaf(av.z, bv.w, acc[2][3]);
            acc[3][0] = fmaf(av.w, bv.x, acc[3][0]);
            acc[3][1] = fmaf(av.w, bv.y, acc[3][1]);
            acc[3][2] = fmaf(av.w, bv.z, acc[3][2]);
            acc[3][3] = fmaf(av.w, bv.w, acc[3][3]);
        }

        // ---- epilogue: + xp, store gates ----
        const float* xp_t = g_xp + (size_t)t * 256 * 1024;
        #pragma unroll
        for (int i = 0; i < 4; i++) {
            int b = b0 + 4 * ty + i;
            size_t off = (size_t)b * 1024 + colbase + 4 * tx;
            float4 xv = *(const float4*)&xp_t[off];
            float4 ov = make_float4(acc[i][0] + xv.x, acc[i][1] + xv.y,
                                    acc[i][2] + xv.z, acc[i][3] + xv.w);
            *(float4*)&g_gates[off] = ov;
        }

        gridbar(tid);

        // ---- pointwise: gate update for 4 (b,h) units ----
        {
            size_t gb = (size_t)pb * 1024 + ph;
            float4 gi = *(const float4*)&g_gates[gb];
            float4 gf = *(const float4*)&g_gates[gb + 256];
            float4 gg = *(const float4*)&g_gates[gb + 512];
            float4 go = *(const float4*)&g_gates[gb + 768];
            size_t cb = (size_t)pb * 256 + ph;
            float4 cp = (t == 0) ? make_float4(0.f, 0.f, 0.f, 0.f)
                                 : *(const float4*)&g_cc[cb];
            float4 cn, hn;
            cn.x = sigf(gf.x) * cp.x + sigf(gi.x) * tanhf(gg.x);
            cn.y = sigf(gf.y) * cp.y + sigf(gi.y) * tanhf(gg.y);
            cn.z = sigf(gf.z) * cp.z + sigf(gi.z) * tanhf(gg.z);
            cn.w = sigf(gf.w) * cp.w + sigf(gi.w) * tanhf(gg.w);
            hn.x = sigf(go.x) * tanhf(cn.x);
            hn.y = sigf(go.y) * tanhf(cn.y);
            hn.z = sigf(go.z) * tanhf(cn.z);
            hn.w = sigf(go.w) * tanhf(cn.w);
            *(float4*)&g_cc[cb] = cn;
            *(float4*)&(hs + (size_t)t * 65536)[cb] = hn;
        }

        gridbar(tid);
    }
}

// ---------------- FC head ----------------
__global__ __launch_bounds__(256) void fc_kernel(
    int stage, const float* __restrict__ W, const float* __restrict__ bias,
    float* __restrict__ dout) {
    __shared__ float As[32][33];
    __shared__ float Ws[32][33];
    const float* A; float* out; int K, N; int relu;
    if (stage == 0) { A = g_y0 + (size_t)76 * 65536; out = g_f1; K = 256; N = 512; relu = 1; }
    else if (stage == 1) { A = g_f1; out = g_f2; K = 512; N = 512; relu = 1; }
    else { A = g_f2; out = dout; K = 512; N = 256; relu = 0; }
    int n0 = blockIdx.x * 32, m0 = blockIdx.y * 32;
    int tid = threadIdx.x;
    int lrow = tid >> 3, lkq = tid & 7;
    int ty = tid >> 4, tx = tid & 15;
    float acc[2][2] = {{0.f, 0.f}, {0.f, 0.f}};
    for (int k0 = 0; k0 < K; k0 += 32) {
        __syncthreads();
        {
            float4 va = *(const float4*)&A[(size_t)(m0 + lrow) * K + k0 + 4 * lkq];
            As[lrow][4*lkq+0] = va.x; As[lrow][4*lkq+1] = va.y;
            As[lrow][4*lkq+2] = va.z; As[lrow][4*lkq+3] = va.w;
            float4 vw = *(const float4*)&W[(size_t)(n0 + lrow) * K + k0 + 4 * lkq];
            Ws[lrow][4*lkq+0] = vw.x; Ws[lrow][4*lkq+1] = vw.y;
            Ws[lrow][4*lkq+2] = vw.z; Ws[lrow][4*lkq+3] = vw.w;
        }
        __syncthreads();
        #pragma unroll
        for (int kk = 0; kk < 32; kk++) {
            float a0 = As[2*ty][kk], a1 = As[2*ty+1][kk];
            float w0 = Ws[2*tx][kk], w1 = Ws[2*tx+1][kk];
            acc[0][0] = fmaf(a0, w0, acc[0][0]);
            acc[0][1] = fmaf(a0, w1, acc[0][1]);
            acc[1][0] = fmaf(a1, w0, acc[1][0]);
            acc[1][1] = fmaf(a1, w1, acc[1][1]);
        }
    }
    #pragma unroll
    for (int i = 0; i < 2; i++) {
        #pragma unroll
        for (int j = 0; j < 2; j++) {
            int m = m0 + 2 * ty + i, n = n0 + 2 * tx + j;
            float v = acc[i][j] + bias[n];
            if (relu) v = fmaxf(v, 0.f);
            out[(size_t)m * N + n] = v;
        }
    }
}

// ---------------- launch ----------------
extern "C" void kernel_launch(void* const* d_in, const int* in_sizes, int n_in,
                              void* d_out, int out_size) {
    const float* x       = (const float*)d_in[0];
    const float* conv_w0 = (const float*)d_in[1];
    const float* conv_b0 = (const float*)d_in[2];
    const float* bn_g0   = (const float*)d_in[3];
    const float* bn_b0   = (const float*)d_in[4];
    const float* bn_m0   = (const float*)d_in[5];
    const float* bn_v0   = (const float*)d_in[6];
    const float* conv_w1 = (const float*)d_in[7];
    const float* conv_b1 = (const float*)d_in[8];
    const float* bn_g1   = (const float*)d_in[9];
    const float* bn_b1   = (const float*)d_in[10];
    const float* bn_m1   = (const float*)d_in[11];
    const float* bn_v1   = (const float*)d_in[12];
    const float* Wih0    = (const float*)d_in[13];
    const float* Whh0    = (const float*)d_in[14];
    const float* bih0    = (const float*)d_in[15];
    const float* bhh0    = (const float*)d_in[16];
    const float* Wih1    = (const float*)d_in[17];
    const float* Whh1    = (const float*)d_in[18];
    const float* bih1    = (const float*)d_in[19];
    const float* bhh1    = (const float*)d_in[20];
    const float* fc0_w   = (const float*)d_in[21];
    const float* fc0_b   = (const float*)d_in[22];
    const float* fc1_w   = (const float*)d_in[23];
    const float* fc1_b   = (const float*)d_in[24];
    const float* out_w   = (const float*)d_in[25];
    const float* out_b   = (const float*)d_in[26];
    float* out = (float*)d_out;

    cudaFuncSetAttribute(lstm_persist_kernel,
                         cudaFuncAttributeMaxDynamicSharedMemorySize, LSTM_SMEM);

    savgol_kernel<<<dim3(40, 256), 256>>>(x);
    conv0_kernel<<<dim3(5, 256), 256>>>(conv_w0, conv_b0, bn_g0, bn_b0, bn_m0, bn_v0);
    conv1_kernel<<<dim3(10, 256), 128>>>(conv_w1, conv_b1, bn_g1, bn_b1, bn_m1, bn_v1);

    gemm_xproj_kernel<<<dim3(8, 154), 256>>>(0, Wih0, bih0, bhh0);
    lstm_persist_kernel<<<NCTA, 128, LSTM_SMEM>>>(0, Whh0);

    gemm_xproj_kernel<<<dim3(8, 154), 256>>>(1, Wih1, bih1, bhh1);
    lstm_persist_kernel<<<NCTA, 128, LSTM_SMEM>>>(1, Whh1);

    fc_kernel<<<dim3(16, 8), 256>>>(0, fc0_w, fc0_b, out);
    fc_kernel<<<dim3(16, 8), 256>>>(1, fc1_w, fc1_b, out);
    fc_kernel<<<dim3(8, 8), 256>>>(2, out_w, out_b, out);
}

// round 4
// speedup vs baseline: 1.4240x; 1.4114x over previous
#include <cuda_runtime.h>
#include <math.h>

// ---------------- scratch (static __device__, allocation-free) ----------------
__device__ float g_sg [256 * 10000];        // savgol output
__device__ float g_y0 [256 * 64 * 624];     // conv block 0 out (b,c,p); reused as layer1 hs
__device__ float g_seq[77 * 256 * 128];     // conv block 1 out, (t,b,c)
__device__ float g_xp [77 * 256 * 1024];    // lstm input projection (t,b,4H), reused per layer
__device__ float g_hs0[77 * 256 * 256];     // layer0 hidden sequence (t,b,H)
__device__ float g_f1 [256 * 512];
__device__ float g_f2 [256 * 512];

__device__ unsigned g_bcnt = 0;             // grid barrier arrive counter
__device__ unsigned g_bgen = 0;             // grid barrier generation (monotonic)

// SG(11,3) interior smoothing taps (symmetric): [-36,9,44,69,84,89,84,69,44,9,-36]/429
__constant__ float c_sg[11] = {
    -36.f/429.f, 9.f/429.f, 44.f/429.f, 69.f/429.f, 84.f/429.f, 89.f/429.f,
    84.f/429.f, 69.f/429.f, 44.f/429.f, 9.f/429.f, -36.f/429.f };

// ---------------- savgol ----------------
__device__ __forceinline__ void sg_fit(const float* __restrict__ xw, double a[4]) {
    double m0 = 0, m1 = 0, m2 = 0, m3 = 0;
    #pragma unroll
    for (int w = 0; w < 11; w++) {
        double y = (double)xw[w]; double t = (double)w;
        m0 += y; m1 += y * t; m2 += y * t * t; m3 += y * t * t * t;
    }
    double M[4][5] = {
        {11.0,    55.0,     385.0,     3025.0,    m0},
        {55.0,    385.0,    3025.0,    25333.0,   m1},
        {385.0,   3025.0,   25333.0,   220825.0,  m2},
        {3025.0,  25333.0,  220825.0,  1978405.0, m3}};
    #pragma unroll
    for (int i = 0; i < 4; i++) {
        double p = M[i][i];
        #pragma unroll
        for (int j = i; j < 5; j++) M[i][j] /= p;
        #pragma unroll
        for (int r = 0; r < 4; r++) {
            if (r != i) {
                double f = M[r][i];
                #pragma unroll
                for (int j = i; j < 5; j++) M[r][j] -= f * M[i][j];
            }
        }
    }
    a[0] = M[0][4]; a[1] = M[1][4]; a[2] = M[2][4]; a[3] = M[3][4];
}

__global__ __launch_bounds__(256) void savgol_kernel(const float* __restrict__ x) {
    int b = blockIdx.y;
    int i = blockIdx.x * 256 + threadIdx.x;
    if (i >= 10000) return;
    const float* xr = x + (size_t)b * 10000;
    float* o = g_sg + (size_t)b * 10000;
    if (i >= 5 && i < 9995) {
        float acc = 0.f;
        #pragma unroll
        for (int j = 0; j < 11; j++) acc = fmaf(xr[i - 5 + j], c_sg[j], acc);
        o[i] = acc;
    } else if (i < 5) {
        double a[4]; sg_fit(xr, a);
        double t = (double)i;
        o[i] = (float)(a[0] + t * (a[1] + t * (a[2] + t * a[3])));
    } else {
        double a[4]; sg_fit(xr + 9989, a);
        double t = (double)(i - 9989);
        o[i] = (float)(a[0] + t * (a[1] + t * (a[2] + t * a[3])));
    }
}

// ---------------- conv block 0 ----------------
__global__ __launch_bounds__(256) void conv0_kernel(
    const float* __restrict__ w, const float* __restrict__ bias,
    const float* __restrict__ bg, const float* __restrict__ bb,
    const float* __restrict__ bm, const float* __restrict__ bv) {
    __shared__ float in_s[2064];
    __shared__ float ws[64][17];
    __shared__ float scs[64], shs[64], bss[64];
    int b = blockIdx.y;
    int p0 = blockIdx.x * 128;
    int tid = threadIdx.x;
    int base = 16 * p0;
    for (int i = tid; i < 2064; i += 256) {
        int col = base + i;
        in_s[i] = (col < 10000) ? g_sg[(size_t)b * 10000 + col] : 0.f;
    }
    for (int i = tid; i < 1024; i += 256) ws[i >> 4][i & 15] = w[i];
    if (tid < 64) {
        float sc = bg[tid] * rsqrtf(bv[tid] + 1e-5f);
        scs[tid] = sc;
        shs[tid] = bb[tid] - bm[tid] * sc;
        bss[tid] = bias[tid];
    }
    __syncthreads();
    int p = p0 + (tid & 127);
    int cb = (tid >> 7) * 32;
    if (p >= 624) return;
    float xr[24];
    int lb = 16 * (tid & 127);
    #pragma unroll
    for (int k = 0; k < 24; k++) xr[k] = in_s[lb + k];
    #pragma unroll 4
    for (int c = cb; c < cb + 32; c++) {
        float s1 = 0.f, s2 = 0.f;
        #pragma unroll
        for (int k = 0; k < 16; k++) {
            float wv = ws[c][k];
            s1 = fmaf(wv, xr[k], s1);
            s2 = fmaf(wv, xr[k + 8], s2);
        }
        float m = fmaxf(fmaxf(s1, s2) + bss[c], 0.f);
        g_y0[((size_t)b * 64 + c) * 624 + p] = scs[c] * m + shs[c];
    }
}

// ---------------- conv block 1 ----------------
__global__ __launch_bounds__(128) void conv1_kernel(
    const float* __restrict__ w, const float* __restrict__ bias,
    const float* __restrict__ bg, const float* __restrict__ bb,
    const float* __restrict__ bm, const float* __restrict__ bv) {
    __shared__ float in_s[64][68];
    __shared__ float ws[4][8][128];
    __shared__ float scs[128], shs[128], bss[128];
    int b = blockIdx.y;
    int p0 = blockIdx.x * 8;
    int tid = threadIdx.x;
    int cg = tid & 31, pg = tid >> 5;

    for (int i = tid; i < 64 * 68; i += 128) {
        int ic = i / 68, cc = i % 68;
        int col = 8 * p0 + cc;
        in_s[ic][cc] = (col < 624) ? g_y0[((size_t)b * 64 + ic) * 624 + col] : 0.f;
    }
    {
        float sc = bg[tid] * rsqrtf(bv[tid] + 1e-5f);
        scs[tid] = sc;
        shs[tid] = bb[tid] - bm[tid] * sc;
        bss[tid] = bias[tid];
    }
    float acc[4][4];
    #pragma unroll
    for (int i = 0; i < 4; i++)
        #pragma unroll
        for (int j = 0; j < 4; j++) acc[i][j] = 0.f;

    for (int ic0 = 0; ic0 < 64; ic0 += 4) {
        __syncthreads();
        #pragma unroll
        for (int icl = 0; icl < 4; icl++) {
            const float4* src = (const float4*)(w + ((size_t)tid * 64 + ic0 + icl) * 8);
            float4 v0 = src[0], v1 = src[1];
            ws[icl][0][tid] = v0.x; ws[icl][1][tid] = v0.y;
            ws[icl][2][tid] = v0.z; ws[icl][3][tid] = v0.w;
            ws[icl][4][tid] = v1.x; ws[icl][5][tid] = v1.y;
            ws[icl][6][tid] = v1.z; ws[icl][7][tid] = v1.w;
        }
        __syncthreads();
        #pragma unroll
        for (int icl = 0; icl < 4; icl++) {
            #pragma unroll
            for (int t = 0; t < 8; t++) {
                float4 w4 = *(const float4*)&ws[icl][t][cg * 4];
                #pragma unroll
                for (int qc = 0; qc < 4; qc++) {
                    float iv = in_s[ic0 + icl][16 * pg + 4 * qc + t];
                    acc[0][qc] = fmaf(w4.x, iv, acc[0][qc]);
                    acc[1][qc] = fmaf(w4.y, iv, acc[1][qc]);
                    acc[2][qc] = fmaf(w4.z, iv, acc[2][qc]);
                    acc[3][qc] = fmaf(w4.w, iv, acc[3][qc]);
                }
            }
        }
    }
    #pragma unroll
    for (int pp = 0; pp < 2; pp++) {
        int p = p0 + 2 * pg + pp;
        if (p >= 77) continue;
        float ov[4];
        #pragma unroll
        for (int i = 0; i < 4; i++) {
            int oc = 4 * cg + i;
            float m = fmaxf(acc[i][2 * pp], acc[i][2 * pp + 1]);
            float v = fmaxf(m + bss[oc], 0.f);
            ov[i] = scs[oc] * v + shs[oc];
        }
        *(float4*)&g_seq[((size_t)p * 256 + b) * 128 + 4 * cg] =
            make_float4(ov[0], ov[1], ov[2], ov[3]);
    }
}

// ---------------- input-projection GEMM: g_xp = A @ Wih^T + (bih + bhh) ----------------
__global__ __launch_bounds__(256) void gemm_xproj_kernel(
    int src, const float* __restrict__ Wih,
    const float* __restrict__ b1, const float* __restrict__ b2) {
    __shared__ float As[16][132];
    __shared__ float Ws[16][132];
    const int K = src ? 256 : 128;
    const float* A = src ? g_hs0 : g_seq;
    int n0 = blockIdx.x * 128, m0 = blockIdx.y * 128;
    int tid = threadIdx.x;
    int lr = tid >> 2, lq = tid & 3;
    int tx = tid & 15, ty = tid >> 4;
    float acc[8][8];
    #pragma unroll
    for (int i = 0; i < 8; i++)
        #pragma unroll
        for (int j = 0; j < 8; j++) acc[i][j] = 0.f;

    for (int k0 = 0; k0 < K; k0 += 16) {
        __syncthreads();
        {
            float4 v;
            v = *(const float4*)&A[(size_t)(m0 + lr) * K + k0 + 4 * lq];
            As[4*lq+0][lr] = v.x; As[4*lq+1][lr] = v.y; As[4*lq+2][lr] = v.z; As[4*lq+3][lr] = v.w;
            v = *(const float4*)&A[(size_t)(m0 + lr + 64) * K + k0 + 4 * lq];
            As[4*lq+0][lr+64] = v.x; As[4*lq+1][lr+64] = v.y; As[4*lq+2][lr+64] = v.z; As[4*lq+3][lr+64] = v.w;
            v = *(const float4*)&Wih[(size_t)(n0 + lr) * K + k0 + 4 * lq];
            Ws[4*lq+0][lr] = v.x; Ws[4*lq+1][lr] = v.y; Ws[4*lq+2][lr] = v.z; Ws[4*lq+3][lr] = v.w;
            v = *(const float4*)&Wih[(size_t)(n0 + lr + 64) * K + k0 + 4 * lq];
            Ws[4*lq+0][lr+64] = v.x; Ws[4*lq+1][lr+64] = v.y; Ws[4*lq+2][lr+64] = v.z; Ws[4*lq+3][lr+64] = v.w;
        }
        __syncthreads();
        #pragma unroll
        for (int kk = 0; kk < 16; kk++) {
            float a[8], bb[8];
            *(float4*)&a[0]  = *(const float4*)&As[kk][8 * ty];
            *(float4*)&a[4]  = *(const float4*)&As[kk][8 * ty + 4];
            *(float4*)&bb[0] = *(const float4*)&Ws[kk][8 * tx];
            *(float4*)&bb[4] = *(const float4*)&Ws[kk][8 * tx + 4];
            #pragma unroll
            for (int i = 0; i < 8; i++)
                #pragma unroll
                for (int j = 0; j < 8; j++)
                    acc[i][j] = fmaf(a[i], bb[j], acc[i][j]);
        }
    }
    float bv[8];
    #pragma unroll
    for (int j = 0; j < 8; j++) {
        int n = n0 + 8 * tx + j;
        bv[j] = b1[n] + b2[n];
    }
    #pragma unroll
    for (int i = 0; i < 8; i++) {
        size_t row = (size_t)(m0 + 8 * ty + i) * 1024 + n0 + 8 * tx;
        float4 o0 = make_float4(acc[i][0]+bv[0], acc[i][1]+bv[1], acc[i][2]+bv[2], acc[i][3]+bv[3]);
        float4 o1 = make_float4(acc[i][4]+bv[4], acc[i][5]+bv[5], acc[i][6]+bv[6], acc[i][7]+bv[7]);
        *(float4*)&g_xp[row]     = o0;
        *(float4*)&g_xp[row + 4] = o1;
    }
}

// ---------------- persistent LSTM layer (v2) ----------------
// 128 CTAs (8 batch-tiles x 16 hidden-tiles) x 256 threads, co-resident.
// CTA tile: 32 batch x 16 hidden x 4 gates. Whh slice in REGISTERS:
// thread(warp w, lane = ks*2+hl): hidden j = w*2+hl, k-slice {kk*16+ks},
// wreg[g][kk] = Whh[g*256+h0+j][kk*16+ks] (64 regs). Split-K partials reduced
// with __shfl_xor over ks lanes. Gates staged in CTA smem; pointwise spread
// over all 256 threads; cell state lives in CTA smem. ONE grid barrier/step.
#define NCTA 128
#define SH 258     // hs_s row stride (floats)

__device__ __forceinline__ void gridbar(int tid) {
    __syncthreads();
    __threadfence();
    if (tid == 0) {
        unsigned gen = *(volatile unsigned*)&g_bgen;
        unsigned my = atomicAdd(&g_bcnt, 1);
        if (my == NCTA - 1) {
            g_bcnt = 0;
            __threadfence();
            atomicAdd(&g_bgen, 1);
        } else {
            while (*(volatile unsigned*)&g_bgen == gen) { }
        }
        __threadfence();
    }
    __syncthreads();
}

__device__ __forceinline__ float sigf(float x) {
    return __fdividef(1.f, 1.f + __expf(-x));
}
__device__ __forceinline__ float tanhfast(float x) {
    return 2.f * sigf(2.f * x) - 1.f;
}

__global__ __launch_bounds__(256) void lstm_persist_kernel(
    int layer, const float* __restrict__ Whh) {
    __shared__ float hs_s[32 * SH];     // h_prev tile, row-major [32][SH]
    __shared__ float gs[32 * 64];       // gate sums [b][g][j]
    __shared__ float c_s[512];          // cell state [b][j], persists across steps

    int tid = threadIdx.x;
    int warp = tid >> 5, lane = tid & 31;
    int ks = lane >> 1, hl = lane & 1;
    int hj = warp * 2 + hl;             // 0..15
    int blk = blockIdx.x;
    int bt = blk >> 4;                  // 0..7
    int ht = blk & 15;                  // 0..15
    int b0 = bt * 32;
    int h0 = ht * 16;
    float* hs = layer ? g_y0 : g_hs0;

    // ---- load Whh slice into registers: wreg[g*16+kk] ----
    float wreg[64];
    #pragma unroll
    for (int g = 0; g < 4; g++) {
        const float* wp = Whh + (size_t)(g * 256 + h0 + hj) * 256 + ks;
        #pragma unroll
        for (int kk = 0; kk < 16; kk++)
            wreg[g * 16 + kk] = wp[kk * 16];
    }

    // ---- init cell state ----
    c_s[2 * tid] = 0.f;
    c_s[2 * tid + 1] = 0.f;

    for (int t = 0; t < 77; t++) {
        // ---- stage h_prev tile (coalesced global read) ----
        __syncthreads();
        {
            int r = tid >> 3, seg = tid & 7;     // row 0..31, 32-float segment
            float* dst = hs_s + r * SH + seg * 32;
            if (t == 0) {
                #pragma unroll
                for (int i = 0; i < 32; i += 2)
                    *(float2*)&dst[i] = make_float2(0.f, 0.f);
            } else {
                const float* src = hs + (size_t)(t - 1) * 65536 + (size_t)(b0 + r) * 256 + seg * 32;
                #pragma unroll
                for (int i = 0; i < 32; i += 4) {
                    float4 v = *(const float4*)&src[i];
                    dst[i + 0] = v.x; dst[i + 1] = v.y;
                    dst[i + 2] = v.z; dst[i + 3] = v.w;
                }
            }
        }
        __syncthreads();

        // ---- recurrent GEMM, 4 chunks of 8 batches ----
        #pragma unroll
        for (int chunk = 0; chunk < 4; chunk++) {
            float acc[8][4];
            #pragma unroll
            for (int bb = 0; bb < 8; bb++)
                #pragma unroll
                for (int g = 0; g < 4; g++) acc[bb][g] = 0.f;

            #pragma unroll
            for (int bb = 0; bb < 8; bb++) {
                const float* ap = hs_s + (chunk * 8 + bb) * SH + ks;
                #pragma unroll
                for (int kk = 0; kk < 16; kk++) {
                    float a = ap[kk * 16];
                    acc[bb][0] = fmaf(a, wreg[kk],      acc[bb][0]);
                    acc[bb][1] = fmaf(a, wreg[16 + kk], acc[bb][1]);
                    acc[bb][2] = fmaf(a, wreg[32 + kk], acc[bb][2]);
                    acc[bb][3] = fmaf(a, wreg[48 + kk], acc[bb][3]);
                }
            }
            // butterfly reduce over ks (lane bits 1..4)
            #pragma unroll
            for (int bb = 0; bb < 8; bb++) {
                #pragma unroll
                for (int g = 0; g < 4; g++) {
                    float v = acc[bb][g];
                    v += __shfl_xor_sync(0xffffffff, v, 2);
                    v += __shfl_xor_sync(0xffffffff, v, 4);
                    v += __shfl_xor_sync(0xffffffff, v, 8);
                    v += __shfl_xor_sync(0xffffffff, v, 16);
                    acc[bb][g] = v;
                }
            }
            if (ks == 0) {
                #pragma unroll
                for (int bb = 0; bb < 8; bb++) {
                    int b = chunk * 8 + bb;
                    #pragma unroll
                    for (int g = 0; g < 4; g++)
                        gs[b * 64 + g * 16 + hj] = acc[bb][g];
                }
            }
        }
        __syncthreads();

        // ---- pointwise: 2 units per thread ----
        {
            const float* xp_t = g_xp + (size_t)t * 256 * 1024;
            float* h_out = hs + (size_t)t * 65536;
            #pragma unroll
            for (int i = 0; i < 2; i++) {
                int u = tid * 2 + i;
                int b = u >> 4, j = u & 15;
                const float* xr = xp_t + (size_t)(b0 + b) * 1024 + h0 + j;
                float gi = gs[b * 64 + j]      + xr[0];
                float gf = gs[b * 64 + 16 + j] + xr[256];
                float gg = gs[b * 64 + 32 + j] + xr[512];
                float go = gs[b * 64 + 48 + j] + xr[768];
                float c = sigf(gf) * c_s[u] + sigf(gi) * tanhfast(gg);
                c_s[u] = c;
                h_out[(size_t)(b0 + b) * 256 + h0 + j] = sigf(go) * tanhfast(c);
            }
        }

        gridbar(tid);
    }
}

// ---------------- FC head ----------------
__global__ __launch_bounds__(256) void fc_kernel(
    int stage, const float* __restrict__ W, const float* __restrict__ bias,
    float* __restrict__ dout) {
    __shared__ float As[32][33];
    __shared__ float Ws[32][33];
    const float* A; float* out; int K, N; int relu;
    if (stage == 0) { A = g_y0 + (size_t)76 * 65536; out = g_f1; K = 256; N = 512; relu = 1; }
    else if (stage == 1) { A = g_f1; out = g_f2; K = 512; N = 512; relu = 1; }
    else { A = g_f2; out = dout; K = 512; N = 256; relu = 0; }
    int n0 = blockIdx.x * 32, m0 = blockIdx.y * 32;
    int tid = threadIdx.x;
    int lrow = tid >> 3, lkq = tid & 7;
    int ty = tid >> 4, tx = tid & 15;
    float acc[2][2] = {{0.f, 0.f}, {0.f, 0.f}};
    for (int k0 = 0; k0 < K; k0 += 32) {
        __syncthreads();
        {
            float4 va = *(const float4*)&A[(size_t)(m0 + lrow) * K + k0 + 4 * lkq];
            As[lrow][4*lkq+0] = va.x; As[lrow][4*lkq+1] = va.y;
            As[lrow][4*lkq+2] = va.z; As[lrow][4*lkq+3] = va.w;
            float4 vw = *(const float4*)&W[(size_t)(n0 + lrow) * K + k0 + 4 * lkq];
            Ws[lrow][4*lkq+0] = vw.x; Ws[lrow][4*lkq+1] = vw.y;
            Ws[lrow][4*lkq+2] = vw.z; Ws[lrow][4*lkq+3] = vw.w;
        }
        __syncthreads();
        #pragma unroll
        for (int kk = 0; kk < 32; kk++) {
            float a0 = As[2*ty][kk], a1 = As[2*ty+1][kk];
            float w0 = Ws[2*tx][kk], w1 = Ws[2*tx+1][kk];
            acc[0][0] = fmaf(a0, w0, acc[0][0]);
            acc[0][1] = fmaf(a0, w1, acc[0][1]);
            acc[1][0] = fmaf(a1, w0, acc[1][0]);
            acc[1][1] = fmaf(a1, w1, acc[1][1]);
        }
    }
    #pragma unroll
    for (int i = 0; i < 2; i++) {
        #pragma unroll
        for (int j = 0; j < 2; j++) {
            int m = m0 + 2 * ty + i, n = n0 + 2 * tx + j;
            float v = acc[i][j] + bias[n];
            if (relu) v = fmaxf(v, 0.f);
            out[(size_t)m * N + n] = v;
        }
    }
}

// ---------------- launch ----------------
extern "C" void kernel_launch(void* const* d_in, const int* in_sizes, int n_in,
                              void* d_out, int out_size) {
    const float* x       = (const float*)d_in[0];
    const float* conv_w0 = (const float*)d_in[1];
    const float* conv_b0 = (const float*)d_in[2];
    const float* bn_g0   = (const float*)d_in[3];
    const float* bn_b0   = (const float*)d_in[4];
    const float* bn_m0   = (const float*)d_in[5];
    const float* bn_v0   = (const float*)d_in[6];
    const float* conv_w1 = (const float*)d_in[7];
    const float* conv_b1 = (const float*)d_in[8];
    const float* bn_g1   = (const float*)d_in[9];
    const float* bn_b1   = (const float*)d_in[10];
    const float* bn_m1   = (const float*)d_in[11];
    const float* bn_v1   = (const float*)d_in[12];
    const float* Wih0    = (const float*)d_in[13];
    const float* Whh0    = (const float*)d_in[14];
    const float* bih0    = (const float*)d_in[15];
    const float* bhh0    = (const float*)d_in[16];
    const float* Wih1    = (const float*)d_in[17];
    const float* Whh1    = (const float*)d_in[18];
    const float* bih1    = (const float*)d_in[19];
    const float* bhh1    = (const float*)d_in[20];
    const float* fc0_w   = (const float*)d_in[21];
    const float* fc0_b   = (const float*)d_in[22];
    const float* fc1_w   = (const float*)d_in[23];
    const float* fc1_b   = (const float*)d_in[24];
    const float* out_w   = (const float*)d_in[25];
    const float* out_b   = (const float*)d_in[26];
    float* out = (float*)d_out;

    savgol_kernel<<<dim3(40, 256), 256>>>(x);
    conv0_kernel<<<dim3(5, 256), 256>>>(conv_w0, conv_b0, bn_g0, bn_b0, bn_m0, bn_v0);
    conv1_kernel<<<dim3(10, 256), 128>>>(conv_w1, conv_b1, bn_g1, bn_b1, bn_m1, bn_v1);

    gemm_xproj_kernel<<<dim3(8, 154), 256>>>(0, Wih0, bih0, bhh0);
    lstm_persist_kernel<<<NCTA, 256>>>(0, Whh0);

    gemm_xproj_kernel<<<dim3(8, 154), 256>>>(1, Wih1, bih1, bhh1);
    lstm_persist_kernel<<<NCTA, 256>>>(1, Whh1);

    fc_kernel<<<dim3(16, 8), 256>>>(0, fc0_w, fc0_b, out);
    fc_kernel<<<dim3(16, 8), 256>>>(1, fc1_w, fc1_b, out);
    fc_kernel<<<dim3(8, 8), 256>>>(2, out_w, out_b, out);
}

// round 5
// speedup vs baseline: 1.4617x; 1.0264x over previous
#include <cuda_runtime.h>
#include <math.h>

// ---------------- scratch (static __device__, allocation-free) ----------------
__device__ float g_sg [256 * 10000];        // savgol output
__device__ float g_y0 [256 * 64 * 624];     // conv block 0 out (b,c,p); reused as layer1 hs
__device__ float g_seq[77 * 256 * 128];     // conv block 1 out, (t,b,c)
__device__ float g_xp [77 * 256 * 1024];    // lstm input projection (t,b,4H), reused per layer
__device__ float g_hs0[77 * 256 * 256];     // layer0 hidden sequence (t,b,H)
__device__ float g_f1 [256 * 512];
__device__ float g_f2 [256 * 512];
__device__ unsigned g_cnt[8];               // per-batch-tile arrival counters

// SG(11,3) interior smoothing taps (symmetric): [-36,9,44,69,84,89,84,69,44,9,-36]/429
__constant__ float c_sg[11] = {
    -36.f/429.f, 9.f/429.f, 44.f/429.f, 69.f/429.f, 84.f/429.f, 89.f/429.f,
    84.f/429.f, 69.f/429.f, 44.f/429.f, 9.f/429.f, -36.f/429.f };

__global__ void reset_cnt_kernel() {
    if (threadIdx.x < 8) g_cnt[threadIdx.x] = 0;
}

// ---------------- savgol ----------------
__device__ __forceinline__ void sg_fit(const float* __restrict__ xw, double a[4]) {
    double m0 = 0, m1 = 0, m2 = 0, m3 = 0;
    #pragma unroll
    for (int w = 0; w < 11; w++) {
        double y = (double)xw[w]; double t = (double)w;
        m0 += y; m1 += y * t; m2 += y * t * t; m3 += y * t * t * t;
    }
    double M[4][5] = {
        {11.0,    55.0,     385.0,     3025.0,    m0},
        {55.0,    385.0,    3025.0,    25333.0,   m1},
        {385.0,   3025.0,   25333.0,   220825.0,  m2},
        {3025.0,  25333.0,  220825.0,  1978405.0, m3}};
    #pragma unroll
    for (int i = 0; i < 4; i++) {
        double p = M[i][i];
        #pragma unroll
        for (int j = i; j < 5; j++) M[i][j] /= p;
        #pragma unroll
        for (int r = 0; r < 4; r++) {
            if (r != i) {
                double f = M[r][i];
                #pragma unroll
                for (int j = i; j < 5; j++) M[r][j] -= f * M[i][j];
            }
        }
    }
    a[0] = M[0][4]; a[1] = M[1][4]; a[2] = M[2][4]; a[3] = M[3][4];
}

__global__ __launch_bounds__(256) void savgol_kernel(const float* __restrict__ x) {
    int b = blockIdx.y;
    int i = blockIdx.x * 256 + threadIdx.x;
    if (i >= 10000) return;
    const float* xr = x + (size_t)b * 10000;
    float* o = g_sg + (size_t)b * 10000;
    if (i >= 5 && i < 9995) {
        float acc = 0.f;
        #pragma unroll
        for (int j = 0; j < 11; j++) acc = fmaf(xr[i - 5 + j], c_sg[j], acc);
        o[i] = acc;
    } else if (i < 5) {
        double a[4]; sg_fit(xr, a);
        double t = (double)i;
        o[i] = (float)(a[0] + t * (a[1] + t * (a[2] + t * a[3])));
    } else {
        double a[4]; sg_fit(xr + 9989, a);
        double t = (double)(i - 9989);
        o[i] = (float)(a[0] + t * (a[1] + t * (a[2] + t * a[3])));
    }
}

// ---------------- conv block 0 ----------------
__global__ __launch_bounds__(256) void conv0_kernel(
    const float* __restrict__ w, const float* __restrict__ bias,
    const float* __restrict__ bg, const float* __restrict__ bb,
    const float* __restrict__ bm, const float* __restrict__ bv) {
    __shared__ float in_s[2064];
    __shared__ float ws[64][17];
    __shared__ float scs[64], shs[64], bss[64];
    int b = blockIdx.y;
    int p0 = blockIdx.x * 128;
    int tid = threadIdx.x;
    int base = 16 * p0;
    for (int i = tid; i < 2064; i += 256) {
        int col = base + i;
        in_s[i] = (col < 10000) ? g_sg[(size_t)b * 10000 + col] : 0.f;
    }
    for (int i = tid; i < 1024; i += 256) ws[i >> 4][i & 15] = w[i];
    if (tid < 64) {
        float sc = bg[tid] * rsqrtf(bv[tid] + 1e-5f);
        scs[tid] = sc;
        shs[tid] = bb[tid] - bm[tid] * sc;
        bss[tid] = bias[tid];
    }
    __syncthreads();
    int p = p0 + (tid & 127);
    int cb = (tid >> 7) * 32;
    if (p >= 624) return;
    float xr[24];
    int lb = 16 * (tid & 127);
    #pragma unroll
    for (int k = 0; k < 24; k++) xr[k] = in_s[lb + k];
    #pragma unroll 4
    for (int c = cb; c < cb + 32; c++) {
        float s1 = 0.f, s2 = 0.f;
        #pragma unroll
        for (int k = 0; k < 16; k++) {
            float wv = ws[c][k];
            s1 = fmaf(wv, xr[k], s1);
            s2 = fmaf(wv, xr[k + 8], s2);
        }
        float m = fmaxf(fmaxf(s1, s2) + bss[c], 0.f);
        g_y0[((size_t)b * 64 + c) * 624 + p] = scs[c] * m + shs[c];
    }
}

// ---------------- conv block 1 ----------------
__global__ __launch_bounds__(128) void conv1_kernel(
    const float* __restrict__ w, const float* __restrict__ bias,
    const float* __restrict__ bg, const float* __restrict__ bb,
    const float* __restrict__ bm, const float* __restrict__ bv) {
    __shared__ float in_s[64][68];
    __shared__ float ws[4][8][128];
    __shared__ float scs[128], shs[128], bss[128];
    int b = blockIdx.y;
    int p0 = blockIdx.x * 8;
    int tid = threadIdx.x;
    int cg = tid & 31, pg = tid >> 5;

    for (int i = tid; i < 64 * 68; i += 128) {
        int ic = i / 68, cc = i % 68;
        int col = 8 * p0 + cc;
        in_s[ic][cc] = (col < 624) ? g_y0[((size_t)b * 64 + ic) * 624 + col] : 0.f;
    }
    {
        float sc = bg[tid] * rsqrtf(bv[tid] + 1e-5f);
        scs[tid] = sc;
        shs[tid] = bb[tid] - bm[tid] * sc;
        bss[tid] = bias[tid];
    }
    float acc[4][4];
    #pragma unroll
    for (int i = 0; i < 4; i++)
        #pragma unroll
        for (int j = 0; j < 4; j++) acc[i][j] = 0.f;

    for (int ic0 = 0; ic0 < 64; ic0 += 4) {
        __syncthreads();
        #pragma unroll
        for (int icl = 0; icl < 4; icl++) {
            const float4* src = (const float4*)(w + ((size_t)tid * 64 + ic0 + icl) * 8);
            float4 v0 = src[0], v1 = src[1];
            ws[icl][0][tid] = v0.x; ws[icl][1][tid] = v0.y;
            ws[icl][2][tid] = v0.z; ws[icl][3][tid] = v0.w;
            ws[icl][4][tid] = v1.x; ws[icl][5][tid] = v1.y;
            ws[icl][6][tid] = v1.z; ws[icl][7][tid] = v1.w;
        }
        __syncthreads();
        #pragma unroll
        for (int icl = 0; icl < 4; icl++) {
            #pragma unroll
            for (int t = 0; t < 8; t++) {
                float4 w4 = *(const float4*)&ws[icl][t][cg * 4];
                #pragma unroll
                for (int qc = 0; qc < 4; qc++) {
                    float iv = in_s[ic0 + icl][16 * pg + 4 * qc + t];
                    acc[0][qc] = fmaf(w4.x, iv, acc[0][qc]);
                    acc[1][qc] = fmaf(w4.y, iv, acc[1][qc]);
                    acc[2][qc] = fmaf(w4.z, iv, acc[2][qc]);
                    acc[3][qc] = fmaf(w4.w, iv, acc[3][qc]);
                }
            }
        }
    }
    #pragma unroll
    for (int pp = 0; pp < 2; pp++) {
        int p = p0 + 2 * pg + pp;
        if (p >= 77) continue;
        float ov[4];
        #pragma unroll
        for (int i = 0; i < 4; i++) {
            int oc = 4 * cg + i;
            float m = fmaxf(acc[i][2 * pp], acc[i][2 * pp + 1]);
            float v = fmaxf(m + bss[oc], 0.f);
            ov[i] = scs[oc] * v + shs[oc];
        }
        *(float4*)&g_seq[((size_t)p * 256 + b) * 128 + 4 * cg] =
            make_float4(ov[0], ov[1], ov[2], ov[3]);
    }
}

// ---------------- input-projection GEMM: g_xp = A @ Wih^T + (bih + bhh) ----------------
// 128x128 tile, 8x8 microtile, register-prefetched k-chunks of 16.
__global__ __launch_bounds__(256) void gemm_xproj_kernel(
    int src, const float* __restrict__ Wih,
    const float* __restrict__ b1, const float* __restrict__ b2) {
    __shared__ float As[16][132];
    __shared__ float Ws[16][132];
    const int K = src ? 256 : 128;
    const float* A = src ? g_hs0 : g_seq;
    int n0 = blockIdx.x * 128, m0 = blockIdx.y * 128;
    int tid = threadIdx.x;
    int lr = tid >> 2, lq = tid & 3;
    int tx = tid & 15, ty = tid >> 4;
    float acc[8][8];
    #pragma unroll
    for (int i = 0; i < 8; i++)
        #pragma unroll
        for (int j = 0; j < 8; j++) acc[i][j] = 0.f;

    const float* a0p = A + (size_t)(m0 + lr) * K + 4 * lq;
    const float* a1p = A + (size_t)(m0 + lr + 64) * K + 4 * lq;
    const float* w0p = Wih + (size_t)(n0 + lr) * K + 4 * lq;
    const float* w1p = Wih + (size_t)(n0 + lr + 64) * K + 4 * lq;

    float4 pa0 = *(const float4*)a0p;
    float4 pa1 = *(const float4*)a1p;
    float4 pw0 = *(const float4*)w0p;
    float4 pw1 = *(const float4*)w1p;

    int nch = K >> 4;
    for (int c = 0; c < nch; c++) {
        As[4*lq+0][lr] = pa0.x; As[4*lq+1][lr] = pa0.y; As[4*lq+2][lr] = pa0.z; As[4*lq+3][lr] = pa0.w;
        As[4*lq+0][lr+64] = pa1.x; As[4*lq+1][lr+64] = pa1.y; As[4*lq+2][lr+64] = pa1.z; As[4*lq+3][lr+64] = pa1.w;
        Ws[4*lq+0][lr] = pw0.x; Ws[4*lq+1][lr] = pw0.y; Ws[4*lq+2][lr] = pw0.z; Ws[4*lq+3][lr] = pw0.w;
        Ws[4*lq+0][lr+64] = pw1.x; Ws[4*lq+1][lr+64] = pw1.y; Ws[4*lq+2][lr+64] = pw1.z; Ws[4*lq+3][lr+64] = pw1.w;
        __syncthreads();
        if (c + 1 < nch) {
            int k0 = (c + 1) * 16;
            pa0 = *(const float4*)(a0p + k0);
            pa1 = *(const float4*)(a1p + k0);
            pw0 = *(const float4*)(w0p + k0);
            pw1 = *(const float4*)(w1p + k0);
        }
        #pragma unroll
        for (int kk = 0; kk < 16; kk++) {
            float a[8], bb[8];
            *(float4*)&a[0]  = *(const float4*)&As[kk][8 * ty];
            *(float4*)&a[4]  = *(const float4*)&As[kk][8 * ty + 4];
            *(float4*)&bb[0] = *(const float4*)&Ws[kk][8 * tx];
            *(float4*)&bb[4] = *(const float4*)&Ws[kk][8 * tx + 4];
            #pragma unroll
            for (int i = 0; i < 8; i++)
                #pragma unroll
                for (int j = 0; j < 8; j++)
                    acc[i][j] = fmaf(a[i], bb[j], acc[i][j]);
        }
        __syncthreads();
    }
    float bv[8];
    #pragma unroll
    for (int j = 0; j < 8; j++) {
        int n = n0 + 8 * tx + j;
        bv[j] = b1[n] + b2[n];
    }
    #pragma unroll
    for (int i = 0; i < 8; i++) {
        size_t row = (size_t)(m0 + 8 * ty + i) * 1024 + n0 + 8 * tx;
        float4 o0 = make_float4(acc[i][0]+bv[0], acc[i][1]+bv[1], acc[i][2]+bv[2], acc[i][3]+bv[3]);
        float4 o1 = make_float4(acc[i][4]+bv[4], acc[i][5]+bv[5], acc[i][6]+bv[6], acc[i][7]+bv[7]);
        *(float4*)&g_xp[row]     = o0;
        *(float4*)&g_xp[row + 4] = o1;
    }
}

// ---------------- persistent LSTM layer (v3: shuffle-free, per-bt barrier) ----------------
// 128 CTAs (8 batch-tiles x 16 hidden-tiles) x 256 threads, 1/SM.
// CTA tile: 32 batch x 64 gatecols (16 hidden x 4 gates), K=256.
// ws_s: k-major [256][64] (64KB), transposed once per launch.
// hs_s: b-major [32][260]. Thread microtile 2b x 4gc, k unrolled x4.
// Sync: per-bt monotonic counters (16 CTAs/group), one arrive+wait per step.
#define NCTA 128
#define HSP 260

__device__ __forceinline__ float sigf(float x) {
    return __fdividef(1.f, 1.f + __expf(-x));
}
__device__ __forceinline__ float tanhfast(float x) {
    return 2.f * sigf(2.f * x) - 1.f;
}

__global__ __launch_bounds__(256) void lstm_persist_kernel(
    int layer, unsigned base, const float* __restrict__ Whh) {
    extern __shared__ float sm[];
    float* ws_s = sm;                    // [256][64] k-major
    float* hs_s = sm + 256 * 64;         // [32][HSP] b-major
    float* gs   = hs_s + 32 * HSP;       // [32][64] gate sums
    float* c_s  = gs + 32 * 64;          // [512] cell state

    int tid = threadIdx.x;
    int blk = blockIdx.x;
    int bt = blk >> 4;                   // 0..7
    int ht = blk & 15;                   // 0..15
    int b0 = bt * 32;
    int h0 = ht * 16;
    float* hs = layer ? g_y0 : g_hs0;

    int by = tid >> 4;                   // 0..15 (2 batches each)
    int gx = tid & 15;                   // 0..15 (4 gatecols each)

    // ---- transpose Whh tile into ws_s[k][gc] (once) ----
    {
        int gc = tid & 63;               // 0..63
        int kseg = tid >> 6;             // 0..3
        int wrow = (gc >> 4) * 256 + h0 + (gc & 15);
        const float* wp = Whh + (size_t)wrow * 256;
        for (int k = kseg * 64; k < kseg * 64 + 64; k++)
            ws_s[k * 64 + gc] = wp[k];
    }

    // ---- init cell state ----
    c_s[2 * tid] = 0.f;
    c_s[2 * tid + 1] = 0.f;

    unsigned* cnt = &g_cnt[bt];

    for (int t = 0; t < 77; t++) {
        // ---- wait for h(t-1) from the other CTAs of this bt group ----
        if (t > 0) {
            if (tid == 0) {
                unsigned target = base + 16u * (unsigned)t;
                while (*(volatile unsigned*)cnt < target) { }
            }
            __syncthreads();
            __threadfence();
        }

        // ---- stage h_prev tile (b-major, coalesced) ----
        {
            int r = tid >> 3, seg = tid & 7;
            float* dst = hs_s + r * HSP + seg * 32;
            if (t == 0) {
                #pragma unroll
                for (int i = 0; i < 32; i += 4)
                    *(float4*)&dst[i] = make_float4(0.f, 0.f, 0.f, 0.f);
            } else {
                const float* src = hs + (size_t)(t - 1) * 65536 + (size_t)(b0 + r) * 256 + seg * 32;
                #pragma unroll
                for (int i = 0; i < 32; i += 4)
                    *(float4*)&dst[i] = *(const float4*)&src[i];
            }
        }
        __syncthreads();

        // ---- recurrent GEMM: 2 batches x 4 gatecols per thread ----
        {
            float acc[2][4];
            #pragma unroll
            for (int i = 0; i < 2; i++)
                #pragma unroll
                for (int j = 0; j < 4; j++) acc[i][j] = 0.f;

            const float* ap0 = hs_s + (2 * by) * HSP;
            const float* ap1 = hs_s + (2 * by + 1) * HSP;
            const float* wp = ws_s + 4 * gx;

            #pragma unroll 2
            for (int k = 0; k < 256; k += 4) {
                float4 a0 = *(const float4*)(ap0 + k);
                float4 a1 = *(const float4*)(ap1 + k);
                float4 w0 = *(const float4*)(wp + (k + 0) * 64);
                float4 w1 = *(const float4*)(wp + (k + 1) * 64);
                float4 w2 = *(const float4*)(wp + (k + 2) * 64);
                float4 w3 = *(const float4*)(wp + (k + 3) * 64);
                acc[0][0] = fmaf(a0.x, w0.x, acc[0][0]);
                acc[0][1] = fmaf(a0.x, w0.y, acc[0][1]);
                acc[0][2] = fmaf(a0.x, w0.z, acc[0][2]);
                acc[0][3] = fmaf(a0.x, w0.w, acc[0][3]);
                acc[1][0] = fmaf(a1.x, w0.x, acc[1][0]);
                acc[1][1] = fmaf(a1.x, w0.y, acc[1][1]);
                acc[1][2] = fmaf(a1.x, w0.z, acc[1][2]);
                acc[1][3] = fmaf(a1.x, w0.w, acc[1][3]);
                acc[0][0] = fmaf(a0.y, w1.x, acc[0][0]);
                acc[0][1] = fmaf(a0.y, w1.y, acc[0][1]);
                acc[0][2] = fmaf(a0.y, w1.z, acc[0][2]);
                acc[0][3] = fmaf(a0.y, w1.w, acc[0][3]);
                acc[1][0] = fmaf(a1.y, w1.x, acc[1][0]);
                acc[1][1] = fmaf(a1.y, w1.y, acc[1][1]);
                acc[1][2] = fmaf(a1.y, w1.z, acc[1][2]);
                acc[1][3] = fmaf(a1.y, w1.w, acc[1][3]);
                acc[0][0] = fmaf(a0.z, w2.x, acc[0][0]);
                acc[0][1] = fmaf(a0.z, w2.y, acc[0][1]);
                acc[0][2] = fmaf(a0.z, w2.z, acc[0][2]);
                acc[0][3] = fmaf(a0.z, w2.w, acc[0][3]);
                acc[1][0] = fmaf(a1.z, w2.x, acc[1][0]);
                acc[1][1] = fmaf(a1.z, w2.y, acc[1][1]);
                acc[1][2] = fmaf(a1.z, w2.z, acc[1][2]);
                acc[1][3] = fmaf(a1.z, w2.w, acc[1][3]);
                acc[0][0] = fmaf(a0.w, w3.x, acc[0][0]);
                acc[0][1] = fmaf(a0.w, w3.y, acc[0][1]);
                acc[0][2] = fmaf(a0.w, w3.z, acc[0][2]);
                acc[0][3] = fmaf(a0.w, w3.w, acc[0][3]);
                acc[1][0] = fmaf(a1.w, w3.x, acc[1][0]);
                acc[1][1] = fmaf(a1.w, w3.y, acc[1][1]);
                acc[1][2] = fmaf(a1.w, w3.z, acc[1][2]);
                acc[1][3] = fmaf(a1.w, w3.w, acc[1][3]);
            }
            *(float4*)&gs[(2 * by) * 64 + 4 * gx] =
                make_float4(acc[0][0], acc[0][1], acc[0][2], acc[0][3]);
            *(float4*)&gs[(2 * by + 1) * 64 + 4 * gx] =
                make_float4(acc[1][0], acc[1][1], acc[1][2], acc[1][3]);
        }
        __syncthreads();

        // ---- pointwise: 2 units per thread; write h(t) ----
        {
            const float* xp_t = g_xp + (size_t)t * 256 * 1024;
            float* h_out = hs + (size_t)t * 65536;
            #pragma unroll
            for (int i = 0; i < 2; i++) {
                int u = tid * 2 + i;
                int b = u >> 4, j = u & 15;
                const float* xr = xp_t + (size_t)(b0 + b) * 1024 + h0 + j;
                float gi = gs[b * 64 + j]      + xr[0];
                float gf = gs[b * 64 + 16 + j] + xr[256];
                float gg = gs[b * 64 + 32 + j] + xr[512];
                float go = gs[b * 64 + 48 + j] + xr[768];
                float c = sigf(gf) * c_s[u] + sigf(gi) * tanhfast(gg);
                c_s[u] = c;
                h_out[(size_t)(b0 + b) * 256 + h0 + j] = sigf(go) * tanhfast(c);
            }
        }

        // ---- arrive ----
        if (t < 76) {
            __threadfence();
            __syncthreads();
            if (tid == 0) atomicAdd(cnt, 1u);
        }
    }
}

// ---------------- FC head ----------------
__global__ __launch_bounds__(256) void fc_kernel(
    int stage, const float* __restrict__ W, const float* __restrict__ bias,
    float* __restrict__ dout) {
    __shared__ float As[32][33];
    __shared__ float Ws[32][33];
    const float* A; float* out; int K, N; int relu;
    if (stage == 0) { A = g_y0 + (size_t)76 * 65536; out = g_f1; K = 256; N = 512; relu = 1; }
    else if (stage == 1) { A = g_f1; out = g_f2; K = 512; N = 512; relu = 1; }
    else { A = g_f2; out = dout; K = 512; N = 256; relu = 0; }
    int n0 = blockIdx.x * 32, m0 = blockIdx.y * 32;
    int tid = threadIdx.x;
    int lrow = tid >> 3, lkq = tid & 7;
    int ty = tid >> 4, tx = tid & 15;
    float acc[2][2] = {{0.f, 0.f}, {0.f, 0.f}};
    for (int k0 = 0; k0 < K; k0 += 32) {
        __syncthreads();
        {
            float4 va = *(const float4*)&A[(size_t)(m0 + lrow) * K + k0 + 4 * lkq];
            As[lrow][4*lkq+0] = va.x; As[lrow][4*lkq+1] = va.y;
            As[lrow][4*lkq+2] = va.z; As[lrow][4*lkq+3] = va.w;
            float4 vw = *(const float4*)&W[(size_t)(n0 + lrow) * K + k0 + 4 * lkq];
            Ws[lrow][4*lkq+0] = vw.x; Ws[lrow][4*lkq+1] = vw.y;
            Ws[lrow][4*lkq+2] = vw.z; Ws[lrow][4*lkq+3] = vw.w;
        }
        __syncthreads();
        #pragma unroll
        for (int kk = 0; kk < 32; kk++) {
            float a0 = As[2*ty][kk], a1 = As[2*ty+1][kk];
            float w0 = Ws[2*tx][kk], w1 = Ws[2*tx+1][kk];
            acc[0][0] = fmaf(a0, w0, acc[0][0]);
            acc[0][1] = fmaf(a0, w1, acc[0][1]);
            acc[1][0] = fmaf(a1, w0, acc[1][0]);
            acc[1][1] = fmaf(a1, w1, acc[1][1]);
        }
    }
    #pragma unroll
    for (int i = 0; i < 2; i++) {
        #pragma unroll
        for (int j = 0; j < 2; j++) {
            int m = m0 + 2 * ty + i, n = n0 + 2 * tx + j;
            float v = acc[i][j] + bias[n];
            if (relu) v = fmaxf(v, 0.f);
            out[(size_t)m * N + n] = v;
        }
    }
}

// ---------------- launch ----------------
#define LSTM_SMEM ((256 * 64 + 32 * HSP + 32 * 64 + 512) * 4)

extern "C" void kernel_launch(void* const* d_in, const int* in_sizes, int n_in,
                              void* d_out, int out_size) {
    const float* x       = (const float*)d_in[0];
    const float* conv_w0 = (const float*)d_in[1];
    const float* conv_b0 = (const float*)d_in[2];
    const float* bn_g0   = (const float*)d_in[3];
    const float* bn_b0   = (const float*)d_in[4];
    const float* bn_m0   = (const float*)d_in[5];
    const float* bn_v0   = (const float*)d_in[6];
    const float* conv_w1 = (const float*)d_in[7];
    const float* conv_b1 = (const float*)d_in[8];
    const float* bn_g1   = (const float*)d_in[9];
    const float* bn_b1   = (const float*)d_in[10];
    const float* bn_m1   = (const float*)d_in[11];
    const float* bn_v1   = (const float*)d_in[12];
    const float* Wih0    = (const float*)d_in[13];
    const float* Whh0    = (const float*)d_in[14];
    const float* bih0    = (const float*)d_in[15];
    const float* bhh0    = (const float*)d_in[16];
    const float* Wih1    = (const float*)d_in[17];
    const float* Whh1    = (const float*)d_in[18];
    const float* bih1    = (const float*)d_in[19];
    const float* bhh1    = (const float*)d_in[20];
    const float* fc0_w   = (const float*)d_in[21];
    const float* fc0_b   = (const float*)d_in[22];
    const float* fc1_w   = (const float*)d_in[23];
    const float* fc1_b   = (const float*)d_in[24];
    const float* out_w   = (const float*)d_in[25];
    const float* out_b   = (const float*)d_in[26];
    float* out = (float*)d_out;

    cudaFuncSetAttribute(lstm_persist_kernel,
                         cudaFuncAttributeMaxDynamicSharedMemorySize, LSTM_SMEM);

    reset_cnt_kernel<<<1, 32>>>();
    savgol_kernel<<<dim3(40, 256), 256>>>(x);
    conv0_kernel<<<dim3(5, 256), 256>>>(conv_w0, conv_b0, bn_g0, bn_b0, bn_m0, bn_v0);
    conv1_kernel<<<dim3(10, 256), 128>>>(conv_w1, conv_b1, bn_g1, bn_b1, bn_m1, bn_v1);

    gemm_xproj_kernel<<<dim3(8, 154), 256>>>(0, Wih0, bih0, bhh0);
    lstm_persist_kernel<<<NCTA, 256, LSTM_SMEM>>>(0, 0u, Whh0);

    gemm_xproj_kernel<<<dim3(8, 154), 256>>>(1, Wih1, bih1, bhh1);
    lstm_persist_kernel<<<NCTA, 256, LSTM_SMEM>>>(1, 16u * 76u, Whh1);

    fc_kernel<<<dim3(16, 8), 256>>>(0, fc0_w, fc0_b, out);
    fc_kernel<<<dim3(16, 8), 256>>>(1, fc1_w, fc1_b, out);
    fc_kernel<<<dim3(8, 8), 256>>>(2, out_w, out_b, out);
}

// round 6
// speedup vs baseline: 1.6533x; 1.1311x over previous
#include <cuda_runtime.h>
#include <math.h>

// ---------------- scratch (static __device__, allocation-free) ----------------
__device__ float g_sg [256 * 10000];        // savgol output
__device__ float g_y0 [256 * 64 * 624];     // conv block 0 out (b,c,p); reused as layer1 hs
__device__ float g_seq[77 * 256 * 128];     // conv block 1 out, (t,b,c)
__device__ float g_xp [77 * 256 * 1024];    // lstm input projection (t,b,4H), reused per layer
__device__ float g_hs0[77 * 256 * 256];     // layer0 hidden sequence (t,b,H)
__device__ float g_f1 [256 * 512];
__device__ float g_f2 [256 * 512];
__device__ unsigned g_cnt[8];               // per-batch-tile arrival counters

// SG(11,3) interior smoothing taps (symmetric): [-36,9,44,69,84,89,84,69,44,9,-36]/429
__constant__ float c_sg[11] = {
    -36.f/429.f, 9.f/429.f, 44.f/429.f, 69.f/429.f, 84.f/429.f, 89.f/429.f,
    84.f/429.f, 69.f/429.f, 44.f/429.f, 9.f/429.f, -36.f/429.f };

__global__ void reset_cnt_kernel() {
    if (threadIdx.x < 8) g_cnt[threadIdx.x] = 0;
}

// ---------------- savgol ----------------
__device__ __forceinline__ void sg_fit(const float* __restrict__ xw, double a[4]) {
    double m0 = 0, m1 = 0, m2 = 0, m3 = 0;
    #pragma unroll
    for (int w = 0; w < 11; w++) {
        double y = (double)xw[w]; double t = (double)w;
        m0 += y; m1 += y * t; m2 += y * t * t; m3 += y * t * t * t;
    }
    double M[4][5] = {
        {11.0,    55.0,     385.0,     3025.0,    m0},
        {55.0,    385.0,    3025.0,    25333.0,   m1},
        {385.0,   3025.0,   25333.0,   220825.0,  m2},
        {3025.0,  25333.0,  220825.0,  1978405.0, m3}};
    #pragma unroll
    for (int i = 0; i < 4; i++) {
        double p = M[i][i];
        #pragma unroll
        for (int j = i; j < 5; j++) M[i][j] /= p;
        #pragma unroll
        for (int r = 0; r < 4; r++) {
            if (r != i) {
                double f = M[r][i];
                #pragma unroll
                for (int j = i; j < 5; j++) M[r][j] -= f * M[i][j];
            }
        }
    }
    a[0] = M[0][4]; a[1] = M[1][4]; a[2] = M[2][4]; a[3] = M[3][4];
}

__global__ __launch_bounds__(256) void savgol_kernel(const float* __restrict__ x) {
    int b = blockIdx.y;
    int i = blockIdx.x * 256 + threadIdx.x;
    if (i >= 10000) return;
    const float* xr = x + (size_t)b * 10000;
    float* o = g_sg + (size_t)b * 10000;
    if (i >= 5 && i < 9995) {
        float acc = 0.f;
        #pragma unroll
        for (int j = 0; j < 11; j++) acc = fmaf(xr[i - 5 + j], c_sg[j], acc);
        o[i] = acc;
    } else if (i < 5) {
        double a[4]; sg_fit(xr, a);
        double t = (double)i;
        o[i] = (float)(a[0] + t * (a[1] + t * (a[2] + t * a[3])));
    } else {
        double a[4]; sg_fit(xr + 9989, a);
        double t = (double)(i - 9989);
        o[i] = (float)(a[0] + t * (a[1] + t * (a[2] + t * a[3])));
    }
}

// ---------------- conv block 0 ----------------
__global__ __launch_bounds__(256) void conv0_kernel(
    const float* __restrict__ w, const float* __restrict__ bias,
    const float* __restrict__ bg, const float* __restrict__ bb,
    const float* __restrict__ bm, const float* __restrict__ bv) {
    __shared__ float in_s[2064];
    __shared__ float ws[64][17];
    __shared__ float scs[64], shs[64], bss[64];
    int b = blockIdx.y;
    int p0 = blockIdx.x * 128;
    int tid = threadIdx.x;
    int base = 16 * p0;
    for (int i = tid; i < 2064; i += 256) {
        int col = base + i;
        in_s[i] = (col < 10000) ? g_sg[(size_t)b * 10000 + col] : 0.f;
    }
    for (int i = tid; i < 1024; i += 256) ws[i >> 4][i & 15] = w[i];
    if (tid < 64) {
        float sc = bg[tid] * rsqrtf(bv[tid] + 1e-5f);
        scs[tid] = sc;
        shs[tid] = bb[tid] - bm[tid] * sc;
        bss[tid] = bias[tid];
    }
    __syncthreads();
    int p = p0 + (tid & 127);
    int cb = (tid >> 7) * 32;
    if (p >= 624) return;
    float xr[24];
    int lb = 16 * (tid & 127);
    #pragma unroll
    for (int k = 0; k < 24; k++) xr[k] = in_s[lb + k];
    #pragma unroll 4
    for (int c = cb; c < cb + 32; c++) {
        float s1 = 0.f, s2 = 0.f;
        #pragma unroll
        for (int k = 0; k < 16; k++) {
            float wv = ws[c][k];
            s1 = fmaf(wv, xr[k], s1);
            s2 = fmaf(wv, xr[k + 8], s2);
        }
        float m = fmaxf(fmaxf(s1, s2) + bss[c], 0.f);
        g_y0[((size_t)b * 64 + c) * 624 + p] = scs[c] * m + shs[c];
    }
}

// ---------------- conv block 1 (v2: 256 threads, 16 pooled pos/CTA, dyn smem) ----------------
// pooled p uses conv pos 2p,2p+1; conv pos c uses in cols 4c..4c+7.
// Block covers pooled [p0, p0+16): in cols [8p0, 8p0+131].
// Threads: cg=tid&31 (4 oc each), pg=tid>>5 (0..7, 2 pooled = 4 conv pos each).
#define C1_IN   (64 * 132)
#define C1_WS   (4 * 8 * 128)
#define C1_SMEM ((C1_IN + C1_WS + 3 * 128) * 4)

__global__ __launch_bounds__(256) void conv1_kernel(
    const float* __restrict__ w, const float* __restrict__ bias,
    const float* __restrict__ bg, const float* __restrict__ bb,
    const float* __restrict__ bm, const float* __restrict__ bv) {
    extern __shared__ float c1s[];
    float* in_s = c1s;                       // [64][132]
    float* ws   = c1s + C1_IN;               // [4][8][128]
    float* scs  = ws + C1_WS;
    float* shs  = scs + 128;
    float* bss  = shs + 128;

    int b = blockIdx.y;
    int p0 = blockIdx.x * 16;
    int tid = threadIdx.x;
    int cg = tid & 31, pg = tid >> 5;

    for (int i = tid; i < C1_IN; i += 256) {
        int ic = i / 132, cc = i % 132;
        int col = 8 * p0 + cc;
        in_s[i] = (col < 624) ? g_y0[((size_t)b * 64 + ic) * 624 + col] : 0.f;
    }
    if (tid < 128) {
        float sc = bg[tid] * rsqrtf(bv[tid] + 1e-5f);
        scs[tid] = sc;
        shs[tid] = bb[tid] - bm[tid] * sc;
        bss[tid] = bias[tid];
    }
    float acc[4][4];
    #pragma unroll
    for (int i = 0; i < 4; i++)
        #pragma unroll
        for (int j = 0; j < 4; j++) acc[i][j] = 0.f;

    int ocl = tid & 127, half = tid >> 7;
    for (int ic0 = 0; ic0 < 64; ic0 += 4) {
        __syncthreads();
        #pragma unroll
        for (int il = 0; il < 2; il++) {
            int icl = half * 2 + il;
            const float4* src = (const float4*)(w + ((size_t)ocl * 64 + ic0 + icl) * 8);
            float4 v0 = src[0], v1 = src[1];
            float* wd = ws + icl * 1024 + ocl;
            wd[0 * 128] = v0.x; wd[1 * 128] = v0.y; wd[2 * 128] = v0.z; wd[3 * 128] = v0.w;
            wd[4 * 128] = v1.x; wd[5 * 128] = v1.y; wd[6 * 128] = v1.z; wd[7 * 128] = v1.w;
        }
        __syncthreads();
        #pragma unroll
        for (int icl = 0; icl < 4; icl++) {
            #pragma unroll
            for (int t = 0; t < 8; t++) {
                float4 w4 = *(const float4*)&ws[icl * 1024 + t * 128 + cg * 4];
                const float* ir = in_s + (ic0 + icl) * 132 + 16 * pg + t;
                #pragma unroll
                for (int qc = 0; qc < 4; qc++) {
                    float iv = ir[4 * qc];
                    acc[0][qc] = fmaf(w4.x, iv, acc[0][qc]);
                    acc[1][qc] = fmaf(w4.y, iv, acc[1][qc]);
                    acc[2][qc] = fmaf(w4.z, iv, acc[2][qc]);
                    acc[3][qc] = fmaf(w4.w, iv, acc[3][qc]);
                }
            }
        }
    }
    #pragma unroll
    for (int pp = 0; pp < 2; pp++) {
        int p = p0 + 2 * pg + pp;
        if (p >= 77) continue;
        float ov[4];
        #pragma unroll
        for (int i = 0; i < 4; i++) {
            int oc = 4 * cg + i;
            float m = fmaxf(acc[i][2 * pp], acc[i][2 * pp + 1]);
            float v = fmaxf(m + bss[oc], 0.f);
            ov[i] = scs[oc] * v + shs[oc];
        }
        *(float4*)&g_seq[((size_t)p * 256 + b) * 128 + 4 * cg] =
            make_float4(ov[0], ov[1], ov[2], ov[3]);
    }
}

// ---------------- input-projection GEMM: g_xp = A @ Wih^T + (bih + bhh) ----------------
__global__ __launch_bounds__(256) void gemm_xproj_kernel(
    int src, const float* __restrict__ Wih,
    const float* __restrict__ b1, const float* __restrict__ b2) {
    __shared__ float As[16][132];
    __shared__ float Ws[16][132];
    const int K = src ? 256 : 128;
    const float* A = src ? g_hs0 : g_seq;
    int n0 = blockIdx.x * 128, m0 = blockIdx.y * 128;
    int tid = threadIdx.x;
    int lr = tid >> 2, lq = tid & 3;
    int tx = tid & 15, ty = tid >> 4;
    float acc[8][8];
    #pragma unroll
    for (int i = 0; i < 8; i++)
        #pragma unroll
        for (int j = 0; j < 8; j++) acc[i][j] = 0.f;

    const float* a0p = A + (size_t)(m0 + lr) * K + 4 * lq;
    const float* a1p = A + (size_t)(m0 + lr + 64) * K + 4 * lq;
    const float* w0p = Wih + (size_t)(n0 + lr) * K + 4 * lq;
    const float* w1p = Wih + (size_t)(n0 + lr + 64) * K + 4 * lq;

    float4 pa0 = *(const float4*)a0p;
    float4 pa1 = *(const float4*)a1p;
    float4 pw0 = *(const float4*)w0p;
    float4 pw1 = *(const float4*)w1p;

    int nch = K >> 4;
    for (int c = 0; c < nch; c++) {
        As[4*lq+0][lr] = pa0.x; As[4*lq+1][lr] = pa0.y; As[4*lq+2][lr] = pa0.z; As[4*lq+3][lr] = pa0.w;
        As[4*lq+0][lr+64] = pa1.x; As[4*lq+1][lr+64] = pa1.y; As[4*lq+2][lr+64] = pa1.z; As[4*lq+3][lr+64] = pa1.w;
        Ws[4*lq+0][lr] = pw0.x; Ws[4*lq+1][lr] = pw0.y; Ws[4*lq+2][lr] = pw0.z; Ws[4*lq+3][lr] = pw0.w;
        Ws[4*lq+0][lr+64] = pw1.x; Ws[4*lq+1][lr+64] = pw1.y; Ws[4*lq+2][lr+64] = pw1.z; Ws[4*lq+3][lr+64] = pw1.w;
        __syncthreads();
        if (c + 1 < nch) {
            int k0 = (c + 1) * 16;
            pa0 = *(const float4*)(a0p + k0);
            pa1 = *(const float4*)(a1p + k0);
            pw0 = *(const float4*)(w0p + k0);
            pw1 = *(const float4*)(w1p + k0);
        }
        #pragma unroll
        for (int kk = 0; kk < 16; kk++) {
            float a[8], bb[8];
            *(float4*)&a[0]  = *(const float4*)&As[kk][8 * ty];
            *(float4*)&a[4]  = *(const float4*)&As[kk][8 * ty + 4];
            *(float4*)&bb[0] = *(const float4*)&Ws[kk][8 * tx];
            *(float4*)&bb[4] = *(const float4*)&Ws[kk][8 * tx + 4];
            #pragma unroll
            for (int i = 0; i < 8; i++)
                #pragma unroll
                for (int j = 0; j < 8; j++)
                    acc[i][j] = fmaf(a[i], bb[j], acc[i][j]);
        }
        __syncthreads();
    }
    float bv[8];
    #pragma unroll
    for (int j = 0; j < 8; j++) {
        int n = n0 + 8 * tx + j;
        bv[j] = b1[n] + b2[n];
    }
    #pragma unroll
    for (int i = 0; i < 8; i++) {
        size_t row = (size_t)(m0 + 8 * ty + i) * 1024 + n0 + 8 * tx;
        float4 o0 = make_float4(acc[i][0]+bv[0], acc[i][1]+bv[1], acc[i][2]+bv[2], acc[i][3]+bv[3]);
        float4 o1 = make_float4(acc[i][4]+bv[4], acc[i][5]+bv[5], acc[i][6]+bv[6], acc[i][7]+bv[7]);
        *(float4*)&g_xp[row]     = o0;
        *(float4*)&g_xp[row + 4] = o1;
    }
}

// ---------------- persistent LSTM layer (v4: register weights + broadcast a) ----------------
// 128 CTAs (8 bt x 16 ht) x 256 threads, 1/SM.
// CTA tile: 32 batch x 64 gatecols (16 hidden x 4 gates), K=256.
// Warp q (0..7) owns k-slice [32q, 32q+32); lane owns gatecols {2*lane, 2*lane+1}
// with Whh in 64 registers. h_prev reads are warp-broadcast LDS (conflict-free).
// Partials ps[8][32][64] in smem, reduced in the pointwise pass.
#define NCTA 128
#define HSP 260
#define PS_OFF (32 * HSP)
#define CS_OFF (PS_OFF + 8 * 32 * 64)
#define LSTM_SMEM ((32 * HSP + 8 * 32 * 64 + 512) * 4)

__device__ __forceinline__ float sigf(float x) {
    return __fdividef(1.f, 1.f + __expf(-x));
}
__device__ __forceinline__ float tanhfast(float x) {
    return 2.f * sigf(2.f * x) - 1.f;
}

__global__ __launch_bounds__(256) void lstm_persist_kernel(
    int layer, unsigned base, const float* __restrict__ Whh) {
    extern __shared__ float sm[];
    float* hs_s = sm;                 // [32][HSP] h_prev tile, b-major
    float* ps   = sm + PS_OFF;        // [8][32][64] split-K partials
    float* c_s  = sm + CS_OFF;        // [512] cell state

    int tid = threadIdx.x;
    int q = tid >> 5;                 // warp id = k-slice
    int lane = tid & 31;
    int blk = blockIdx.x;
    int bt = blk >> 4, ht = blk & 15;
    int b0 = bt * 32, h0 = ht * 16;
    float* hs = layer ? g_y0 : g_hs0;

    // ---- Whh slice into registers (once per launch) ----
    float w0r[32], w1r[32];
    {
        int gc0 = 2 * lane, gc1 = 2 * lane + 1;
        const float* r0 = Whh + (size_t)((gc0 >> 4) * 256 + h0 + (gc0 & 15)) * 256 + q * 32;
        const float* r1 = Whh + (size_t)((gc1 >> 4) * 256 + h0 + (gc1 & 15)) * 256 + q * 32;
        #pragma unroll
        for (int k = 0; k < 32; k++) { w0r[k] = r0[k]; w1r[k] = r1[k]; }
    }
    c_s[2 * tid] = 0.f;
    c_s[2 * tid + 1] = 0.f;
    unsigned* cnt = &g_cnt[bt];

    for (int t = 0; t < 77; t++) {
        // ---- wait for h(t-1) from the other CTAs of this bt group ----
        if (t > 0) {
            if (tid == 0) {
                unsigned target = base + 16u * (unsigned)t;
                while (*(volatile unsigned*)cnt < target) { }
            }
            __syncthreads();
            __threadfence();
        }

        // ---- stage h_prev tile ----
        {
            int r = tid >> 3, seg = tid & 7;
            float* dst = hs_s + r * HSP + seg * 32;
            if (t == 0) {
                #pragma unroll
                for (int i = 0; i < 32; i += 4)
                    *(float4*)&dst[i] = make_float4(0.f, 0.f, 0.f, 0.f);
            } else {
                const float* src = hs + (size_t)(t - 1) * 65536 + (size_t)(b0 + r) * 256 + seg * 32;
                #pragma unroll
                for (int i = 0; i < 32; i += 4)
                    *(float4*)&dst[i] = *(const float4*)&src[i];
            }
        }
        __syncthreads();

        // ---- split-K GEMM: 32 batches x 2 gatecols, k-slice of 32 ----
        {
            const float* ap = hs_s + q * 32;
            float* pq = ps + q * 2048 + 2 * lane;
            #pragma unroll 2
            for (int b = 0; b < 32; b++) {
                const float* a = ap + b * HSP;
                float s0 = 0.f, s1 = 0.f;
                #pragma unroll
                for (int k = 0; k < 32; k += 4) {
                    float4 av = *(const float4*)(a + k);
                    s0 = fmaf(av.x, w0r[k + 0], s0); s1 = fmaf(av.x, w1r[k + 0], s1);
                    s0 = fmaf(av.y, w0r[k + 1], s0); s1 = fmaf(av.y, w1r[k + 1], s1);
                    s0 = fmaf(av.z, w0r[k + 2], s0); s1 = fmaf(av.z, w1r[k + 2], s1);
                    s0 = fmaf(av.w, w0r[k + 3], s0); s1 = fmaf(av.w, w1r[k + 3], s1);
                }
                *(float2*)(pq + b * 64) = make_float2(s0, s1);
            }
        }
        __syncthreads();

        // ---- pointwise: reduce 8 partials + xp, update c/h (2 units/thread) ----
        {
            const float* xp_t = g_xp + (size_t)t * 256 * 1024;
            float* h_out = hs + (size_t)t * 65536;
            #pragma unroll
            for (int i = 0; i < 2; i++) {
                int u = 2 * tid + i;
                int b = u >> 4, j = u & 15;
                float gi = 0.f, gf = 0.f, gg = 0.f, go = 0.f;
                #pragma unroll
                for (int qq = 0; qq < 8; qq++) {
                    const float* p = ps + qq * 2048 + b * 64;
                    gi += p[j]; gf += p[16 + j]; gg += p[32 + j]; go += p[48 + j];
                }
                const float* xr = xp_t + (size_t)(b0 + b) * 1024 + h0 + j;
                gi += xr[0]; gf += xr[256]; gg += xr[512]; go += xr[768];
                float c = sigf(gf) * c_s[u] + sigf(gi) * tanhfast(gg);
                c_s[u] = c;
                h_out[(size_t)(b0 + b) * 256 + h0 + j] = sigf(go) * tanhfast(c);
            }
        }

        // ---- arrive ----
        if (t < 76) {
            __threadfence();
            __syncthreads();
            if (tid == 0) atomicAdd(cnt, 1u);
        }
    }
}

// ---------------- FC head ----------------
__global__ __launch_bounds__(256) void fc_kernel(
    int stage, const float* __restrict__ W, const float* __restrict__ bias,
    float* __restrict__ dout) {
    __shared__ float As[32][33];
    __shared__ float Ws[32][33];
    const float* A; float* out; int K, N; int relu;
    if (stage == 0) { A = g_y0 + (size_t)76 * 65536; out = g_f1; K = 256; N = 512; relu = 1; }
    else if (stage == 1) { A = g_f1; out = g_f2; K = 512; N = 512; relu = 1; }
    else { A = g_f2; out = dout; K = 512; N = 256; relu = 0; }
    int n0 = blockIdx.x * 32, m0 = blockIdx.y * 32;
    int tid = threadIdx.x;
    int lrow = tid >> 3, lkq = tid & 7;
    int ty = tid >> 4, tx = tid & 15;
    float acc[2][2] = {{0.f, 0.f}, {0.f, 0.f}};
    for (int k0 = 0; k0 < K; k0 += 32) {
        __syncthreads();
        {
            float4 va = *(const float4*)&A[(size_t)(m0 + lrow) * K + k0 + 4 * lkq];
            As[lrow][4*lkq+0] = va.x; As[lrow][4*lkq+1] = va.y;
            As[lrow][4*lkq+2] = va.z; As[lrow][4*lkq+3] = va.w;
            float4 vw = *(const float4*)&W[(size_t)(n0 + lrow) * K + k0 + 4 * lkq];
            Ws[lrow][4*lkq+0] = vw.x; Ws[lrow][4*lkq+1] = vw.y;
            Ws[lrow][4*lkq+2] = vw.z; Ws[lrow][4*lkq+3] = vw.w;
        }
        __syncthreads();
        #pragma unroll
        for (int kk = 0; kk < 32; kk++) {
            float a0 = As[2*ty][kk], a1 = As[2*ty+1][kk];
            float w0 = Ws[2*tx][kk], w1 = Ws[2*tx+1][kk];
            acc[0][0] = fmaf(a0, w0, acc[0][0]);
            acc[0][1] = fmaf(a0, w1, acc[0][1]);
            acc[1][0] = fmaf(a1, w0, acc[1][0]);
            acc[1][1] = fmaf(a1, w1, acc[1][1]);
        }
    }
    #pragma unroll
    for (int i = 0; i < 2; i++) {
        #pragma unroll
        for (int j = 0; j < 2; j++) {
            int m = m0 + 2 * ty + i, n = n0 + 2 * tx + j;
            float v = acc[i][j] + bias[n];
            if (relu) v = fmaxf(v, 0.f);
            out[(size_t)m * N + n] = v;
        }
    }
}

// ---------------- launch ----------------
extern "C" void kernel_launch(void* const* d_in, const int* in_sizes, int n_in,
                              void* d_out, int out_size) {
    const float* x       = (const float*)d_in[0];
    const float* conv_w0 = (const float*)d_in[1];
    const float* conv_b0 = (const float*)d_in[2];
    const float* bn_g0   = (const float*)d_in[3];
    const float* bn_b0   = (const float*)d_in[4];
    const float* bn_m0   = (const float*)d_in[5];
    const float* bn_v0   = (const float*)d_in[6];
    const float* conv_w1 = (const float*)d_in[7];
    const float* conv_b1 = (const float*)d_in[8];
    const float* bn_g1   = (const float*)d_in[9];
    const float* bn_b1   = (const float*)d_in[10];
    const float* bn_m1   = (const float*)d_in[11];
    const float* bn_v1   = (const float*)d_in[12];
    const float* Wih0    = (const float*)d_in[13];
    const float* Whh0    = (const float*)d_in[14];
    const float* bih0    = (const float*)d_in[15];
    const float* bhh0    = (const float*)d_in[16];
    const float* Wih1    = (const float*)d_in[17];
    const float* Whh1    = (const float*)d_in[18];
    const float* bih1    = (const float*)d_in[19];
    const float* bhh1    = (const float*)d_in[20];
    const float* fc0_w   = (const float*)d_in[21];
    const float* fc0_b   = (const float*)d_in[22];
    const float* fc1_w   = (const float*)d_in[23];
    const float* fc1_b   = (const float*)d_in[24];
    const float* out_w   = (const float*)d_in[25];
    const float* out_b   = (const float*)d_in[26];
    float* out = (float*)d_out;

    cudaFuncSetAttribute(lstm_persist_kernel,
                         cudaFuncAttributeMaxDynamicSharedMemorySize, LSTM_SMEM);
    cudaFuncSetAttribute(conv1_kernel,
                         cudaFuncAttributeMaxDynamicSharedMemorySize, C1_SMEM);

    reset_cnt_kernel<<<1, 32>>>();
    savgol_kernel<<<dim3(40, 256), 256>>>(x);
    conv0_kernel<<<dim3(5, 256), 256>>>(conv_w0, conv_b0, bn_g0, bn_b0, bn_m0, bn_v0);
    conv1_kernel<<<dim3(5, 256), 256, C1_SMEM>>>(conv_w1, conv_b1, bn_g1, bn_b1, bn_m1, bn_v1);

    gemm_xproj_kernel<<<dim3(8, 154), 256>>>(0, Wih0, bih0, bhh0);
    lstm_persist_kernel<<<NCTA, 256, LSTM_SMEM>>>(0, 0u, Whh0);

    gemm_xproj_kernel<<<dim3(8, 154), 256>>>(1, Wih1, bih1, bhh1);
    lstm_persist_kernel<<<NCTA, 256, LSTM_SMEM>>>(1, 16u * 76u, Whh1);

    fc_kernel<<<dim3(16, 8), 256>>>(0, fc0_w, fc0_b, out);
    fc_kernel<<<dim3(16, 8), 256>>>(1, fc1_w, fc1_b, out);
    fc_kernel<<<dim3(8, 8), 256>>>(2, out_w, out_b, out);
}